// round 9
// baseline (speedup 1.0000x reference)
#include <cuda_runtime.h>
#include <cuda_bf16.h>
#include <math.h>
#include <stdint.h>

#define BB   2048
#define INN  512
#define HH   512
#define KFR  32
#define OUTN 512
#define KD   1536            // IN + 2H (combined_d width)
#define KC   1024            // IN + H
#define BH   (BB*HH)

#define OFF_WI   0
#define OFF_WO   (512*1024)
#define OFF_WC   (2*512*1024)
#define OFF_WF   (3*512*1024)
#define OFF_WOUT (3*512*1024 + 512*1536)
#define W_TOTAL  (OFF_WOUT + 512*512)

#define TILE_B   16384       // one 128x64 bf16 tile in smem
#define STAGE_B  (4*TILE_B)  // Ahi, Alo, Bhi, Blo
#define NSTAGE   3
#define SMEM_TOT (NSTAGE*STAGE_B)   // 196608

// ---------------- static device scratch ----------------
__device__ __nv_bfloat16 g_comb_hi[BB*KD];
__device__ __nv_bfloat16 g_comb_lo[BB*KD];
__device__ __nv_bfloat16 g_w_hi[W_TOTAL];
__device__ __nv_bfloat16 g_w_lo[W_TOTAL];
__device__ __nv_bfloat16 g_hid_hi[BH];
__device__ __nv_bfloat16 g_hid_lo[BH];
__device__ float g_z[4][BH];          // pre-activations: 0=i, 1=o, 2=c, 3=f

// ---------------- PTX helpers (baseline ISA only) ----------------
__device__ __forceinline__ uint32_t smem_u32(const void* p) {
    return (uint32_t)__cvta_generic_to_shared(p);
}

__device__ __forceinline__ void cp16(uint32_t daddr, const void* g) {
    asm volatile("cp.async.cg.shared.global [%0], [%1], 16;" :: "r"(daddr), "l"(g) : "memory");
}
#define CP_COMMIT() asm volatile("cp.async.commit_group;" ::: "memory")
template <int N>
__device__ __forceinline__ void cp_wait() {
    asm volatile("cp.async.wait_group %0;" :: "n"(N) : "memory");
}

__device__ __forceinline__ void ldsm4(uint32_t addr, uint32_t* r) {
    asm volatile("ldmatrix.sync.aligned.m8n8.x4.shared.b16 {%0,%1,%2,%3}, [%4];"
        : "=r"(r[0]), "=r"(r[1]), "=r"(r[2]), "=r"(r[3]) : "r"(addr));
}

__device__ __forceinline__ void mma_bf16(float* c, const uint32_t* a, const uint32_t* b) {
    asm volatile("mma.sync.aligned.m16n8k16.row.col.f32.bf16.bf16.f32 "
        "{%0,%1,%2,%3}, {%4,%5,%6,%7}, {%8,%9}, {%0,%1,%2,%3};"
        : "+f"(c[0]), "+f"(c[1]), "+f"(c[2]), "+f"(c[3])
        : "r"(a[0]), "r"(a[1]), "r"(a[2]), "r"(a[3]), "r"(b[0]), "r"(b[1]));
}

// ---------------------------------------------------------------------------
// cp.async loader: one K-chunk (64 cols) of the 4 tiles into one stage.
// swizzle: phys_col16 = col16 ^ (row & 7)
// ---------------------------------------------------------------------------
__device__ __forceinline__ void load_stage(uint32_t sbase,
    const char* a_hi, const char* a_lo, const char* b_hi, const char* b_lo,
    int lda_b, int ldb_b, int k0b, int tid) {
    const char* srcs[4] = {a_hi, a_lo, b_hi, b_lo};
    const int lds[4] = {lda_b, lda_b, ldb_b, ldb_b};
#pragma unroll
    for (int t = 0; t < 4; t++) {
#pragma unroll
        for (int i = 0; i < 4; i++) {
            int idx = i * 256 + tid;
            int row = idx >> 3;
            uint32_t ch = (uint32_t)(idx & 7) * 16;
            uint32_t off = (uint32_t)row * 128 + (ch ^ (((uint32_t)row & 7) << 4));
            cp16(sbase + t * TILE_B + off,
                 srcs[t] + (size_t)row * lds[t] + k0b + ch);
        }
    }
}

// ---------------------------------------------------------------------------
// split-bf16 mma.sync GEMM tile (R4-best: 128x128, 8 warps, 3-stage, chunk 64)
// ---------------------------------------------------------------------------
__device__ __forceinline__ void mma_gemm_tile(
    const __nv_bfloat16* Ahi, const __nv_bfloat16* Alo, int lda,
    const __nv_bfloat16* Bhi, const __nv_bfloat16* Blo, int ldb,
    const float* __restrict__ bias, float* __restrict__ C, int ldc,
    int K, int blockM, int blockN) {
    extern __shared__ __align__(1024) char dsm[];
    const int tid  = threadIdx.x;
    const int lane = tid & 31;
    const int wid  = tid >> 5;
    const int wm   = wid & 3;
    const int wn   = wid >> 2;
    uint32_t sb = smem_u32(dsm);

    const uint32_t a_kb = ((uint32_t)lane >> 4) * 16;
    const uint32_t b_kb = (((uint32_t)lane >> 3) & 1) * 16;
    uint32_t aRow[2], aXor[2];
#pragma unroll
    for (int mt = 0; mt < 2; mt++) {
        int r = wm * 32 + mt * 16 + (lane & 15);
        aRow[mt] = (uint32_t)r * 128;
        aXor[mt] = ((uint32_t)r & 7) << 4;
    }
    uint32_t bRow[4], bXor[4];
#pragma unroll
    for (int g = 0; g < 4; g++) {
        int r = wn * 64 + g * 16 + (((lane >> 4) << 3) + (lane & 7));
        bRow[g] = (uint32_t)r * 128;
        bXor[g] = ((uint32_t)r & 7) << 4;
    }

    float acc[2][8][4];
#pragma unroll
    for (int mt = 0; mt < 2; mt++)
#pragma unroll
        for (int nt = 0; nt < 8; nt++)
#pragma unroll
            for (int j = 0; j < 4; j++) acc[mt][nt][j] = 0.0f;

    const char* aH = (const char*)(Ahi + (size_t)blockM * lda);
    const char* aL = (const char*)(Alo + (size_t)blockM * lda);
    const char* bH = (const char*)(Bhi + (size_t)blockN * ldb);
    const char* bL = (const char*)(Blo + (size_t)blockN * ldb);
    const int lda_b = lda * 2, ldb_b = ldb * 2;
    const int NC = K / 64;

    load_stage(sb, aH, aL, bH, bL, lda_b, ldb_b, 0, tid);
    CP_COMMIT();
    load_stage(sb + STAGE_B, aH, aL, bH, bL, lda_b, ldb_b, 128, tid);
    CP_COMMIT();

    int stage = 0;
    for (int c = 0; c < NC; ++c) {
        cp_wait<1>();
        __syncthreads();
        if (c + 2 < NC) {
            int s2 = stage + 2; if (s2 >= NSTAGE) s2 -= NSTAGE;
            load_stage(sb + (uint32_t)s2 * STAGE_B, aH, aL, bH, bL,
                       lda_b, ldb_b, (c + 2) * 128, tid);
        }
        CP_COMMIT();

        const uint32_t st = sb + (uint32_t)stage * STAGE_B;
#pragma unroll
        for (int kk = 0; kk < 4; kk++) {
            uint32_t ah[2][4], al[2][4];
#pragma unroll
            for (int mt = 0; mt < 2; mt++) {
                uint32_t col = ((uint32_t)(kk * 32) + a_kb) ^ aXor[mt];
                ldsm4(st + 0 * TILE_B + aRow[mt] + col, ah[mt]);
                ldsm4(st + 1 * TILE_B + aRow[mt] + col, al[mt]);
            }
            uint32_t bh[8][2], bl[8][2];
#pragma unroll
            for (int g = 0; g < 4; g++) {
                uint32_t col = ((uint32_t)(kk * 32) + b_kb) ^ bXor[g];
                uint32_t r[4];
                ldsm4(st + 2 * TILE_B + bRow[g] + col, r);
                bh[2*g][0] = r[0]; bh[2*g][1] = r[1];
                bh[2*g+1][0] = r[2]; bh[2*g+1][1] = r[3];
                ldsm4(st + 3 * TILE_B + bRow[g] + col, r);
                bl[2*g][0] = r[0]; bl[2*g][1] = r[1];
                bl[2*g+1][0] = r[2]; bl[2*g+1][1] = r[3];
            }
#pragma unroll
            for (int mt = 0; mt < 2; mt++)
#pragma unroll
                for (int nt = 0; nt < 8; nt++) {
                    mma_bf16(acc[mt][nt], ah[mt], bh[nt]);
                    mma_bf16(acc[mt][nt], ah[mt], bl[nt]);
                    mma_bf16(acc[mt][nt], al[mt], bh[nt]);
                }
        }
        if (++stage >= NSTAGE) stage = 0;
    }

#pragma unroll
    for (int mt = 0; mt < 2; mt++) {
        int r0 = blockM + wm * 32 + mt * 16 + (lane >> 2);
#pragma unroll
        for (int nt = 0; nt < 8; nt++) {
            int col = blockN + wn * 64 + nt * 8 + (lane & 3) * 2;
            float b0 = bias[col], b1 = bias[col + 1];
            float2 v0 = {acc[mt][nt][0] + b0, acc[mt][nt][1] + b1};
            float2 v1 = {acc[mt][nt][2] + b0, acc[mt][nt][3] + b1};
            *(float2*)(C + (size_t)r0 * ldc + col) = v0;
            *(float2*)(C + (size_t)(r0 + 8) * ldc + col) = v1;
        }
    }
}

// ---------------------------------------------------------------------------
__global__ __launch_bounds__(256, 1)
void gates_mma_kernel(const float* __restrict__ bi, const float* __restrict__ bo,
                      const float* __restrict__ bc, const float* __restrict__ bf) {
    int z = blockIdx.z;
    const __nv_bfloat16 *wh, *wl; const float* bias; int K; float* dst;
    if      (z == 0) { wh = g_w_hi + OFF_WF; wl = g_w_lo + OFF_WF; bias = bf; K = KD; dst = g_z[3]; }
    else if (z == 1) { wh = g_w_hi + OFF_WI; wl = g_w_lo + OFF_WI; bias = bi; K = KC; dst = g_z[0]; }
    else if (z == 2) { wh = g_w_hi + OFF_WO; wl = g_w_lo + OFF_WO; bias = bo; K = KC; dst = g_z[1]; }
    else             { wh = g_w_hi + OFF_WC; wl = g_w_lo + OFF_WC; bias = bc; K = KC; dst = g_z[2]; }
    mma_gemm_tile(g_comb_hi, g_comb_lo, KD, wh, wl, K, bias, dst, HH, K,
                  blockIdx.y * 128, blockIdx.x * 128);
}

__global__ __launch_bounds__(256, 1)
void out_mma_kernel(const float* __restrict__ bout, float* __restrict__ out) {
    mma_gemm_tile(g_hid_hi, g_hid_lo, HH,
                  g_w_hi + OFF_WOUT, g_w_lo + OFF_WOUT, HH,
                  bout, out, OUTN, HH, blockIdx.y * 128, blockIdx.x * 128);
}

// ---------------------------------------------------------------------------
// h_c_1 bulk copy: runs on a forked stream, overlapping the gates GEMM.
// h_c_1[0..30] = cell_tensor[1..31]  (one contiguous 31*BH-float block)
// ---------------------------------------------------------------------------
__global__ __launch_bounds__(256)
void hc_copy_kernel(const float* __restrict__ cell_t, float* __restrict__ dout) {
    const float4* src = (const float4*)(cell_t + BH);
    float4* dst = (float4*)(dout + (size_t)2 * BB * OUTN);
    const int n = 31 * BH / 4;
    int stride = gridDim.x * blockDim.x;
    for (int i = blockIdx.x * blockDim.x + threadIdx.x; i < n; i += stride * 4) {
        float4 v0 = src[i];
        float4 v1 = (i + stride     < n) ? src[i + stride]     : v0;
        float4 v2 = (i + stride * 2 < n) ? src[i + stride * 2] : v0;
        float4 v3 = (i + stride * 3 < n) ? src[i + stride * 3] : v0;
        dst[i] = v0;
        if (i + stride     < n) dst[i + stride]     = v1;
        if (i + stride * 2 < n) dst[i + stride * 2] = v2;
        if (i + stride * 3 < n) dst[i + stride * 3] = v3;
    }
}

// ---------------------------------------------------------------------------
// conversions: fp32 -> bf16 hi/lo split
// ---------------------------------------------------------------------------
__device__ __forceinline__ void split4(float4 v, __nv_bfloat16* hi, __nv_bfloat16* lo) {
    float f[4] = {v.x, v.y, v.z, v.w};
    union { __nv_bfloat16 h[4]; uint2 u; } H, L;
#pragma unroll
    for (int i = 0; i < 4; i++) {
        __nv_bfloat16 h = __float2bfloat16_rn(f[i]);
        H.h[i] = h;
        L.h[i] = __float2bfloat16_rn(f[i] - __bfloat162float(h));
    }
    *(uint2*)hi = H.u;
    *(uint2*)lo = L.u;
}

__global__ void comb_conv_kernel(const float* __restrict__ sample,
                                 const float* __restrict__ hidden,
                                 const float* __restrict__ d0) {
    int idx = blockIdx.x * blockDim.x + threadIdx.x;
    if (idx >= BB * KD / 4) return;
    int b  = idx / (KD / 4);
    int c4 = idx % (KD / 4);
    float4 v;
    if (c4 < INN / 4)            v = ((const float4*)sample)[b * (INN/4) + c4];
    else if (c4 < (INN+HH) / 4)  v = ((const float4*)hidden)[b * (HH/4) + (c4 - INN/4)];
    else                         v = ((const float4*)d0)[b * (HH/4) + (c4 - (INN+HH)/4)];
    split4(v, g_comb_hi + idx * 4, g_comb_lo + idx * 4);
}

__global__ void w_conv_kernel(const float* __restrict__ Wi, const float* __restrict__ Wo,
                              const float* __restrict__ Wc, const float* __restrict__ Wf,
                              const float* __restrict__ Wout) {
    int a = blockIdx.y;
    const float* src; size_t off; int n;
    if      (a == 0) { src = Wi;   off = OFF_WI;   n = 512 * 1024; }
    else if (a == 1) { src = Wo;   off = OFF_WO;   n = 512 * 1024; }
    else if (a == 2) { src = Wc;   off = OFF_WC;   n = 512 * 1024; }
    else if (a == 3) { src = Wf;   off = OFF_WF;   n = 512 * 1536; }
    else             { src = Wout; off = OFF_WOUT; n = 512 * 512;  }
    int i = blockIdx.x * blockDim.x + threadIdx.x;
    if (i * 4 >= n) return;
    float4 v = ((const float4*)src)[i];
    split4(v, g_w_hi + off + (size_t)i * 4, g_w_lo + off + (size_t)i * 4);
}

// ---------------------------------------------------------------------------
// fused elementwise (no bulk copy), 4-slice batched loads for MLP
// ---------------------------------------------------------------------------
__device__ __forceinline__ float sigf(float x) { return 1.0f / (1.0f + expf(-x)); }

__global__ void fused_cell_kernel(const float* __restrict__ cell_t,
                                  float* __restrict__ dout) {
    int idx = blockIdx.x * blockDim.x + threadIdx.x;   // over BH/4
    const int nb4 = BH / 4;
    if (idx >= nb4) return;

    const float4* c4  = (const float4*)cell_t;
    float4* hid = (float4*)(dout + (size_t)BB * OUTN);
    float4* hc  = (float4*)(dout + (size_t)2 * BB * OUTN);
    float4* dv  = (float4*)(dout + (size_t)2 * BB * OUTN + (size_t)KFR * BH);

    float4 zf = ((const float4*)g_z[3])[idx];
    float4 d;
    d.x = 0.5f * sigf(zf.x); d.y = 0.5f * sigf(zf.y);
    d.z = 0.5f * sigf(zf.z); d.w = 0.5f * sigf(zf.w);
    dv[idx] = d;

    float4 w   = make_float4(1.f, 1.f, 1.f, 1.f);
    float4 acc = make_float4(0.f, 0.f, 0.f, 0.f);
#pragma unroll
    for (int jb = KFR - 1; jb >= 0; jb -= 4) {
        float4 buf[4];                               // 4 slices in flight
#pragma unroll
        for (int u = 0; u < 4; u++)
            buf[u] = c4[(size_t)(jb - u) * nb4 + idx];
#pragma unroll
        for (int u = 0; u < 4; u++) {
            int j = jb - u;
            float fi  = (float)(KFR - 1 - j);
            float inv = 1.0f / (float)(KFR - j);
            w.x *= (fi - d.x) * inv;  w.y *= (fi - d.y) * inv;
            w.z *= (fi - d.z) * inv;  w.w *= (fi - d.w) * inv;
            acc.x = fmaf(w.x, buf[u].x, acc.x);  acc.y = fmaf(w.y, buf[u].y, acc.y);
            acc.z = fmaf(w.z, buf[u].z, acc.z);  acc.w = fmaf(w.w, buf[u].w, acc.w);
        }
    }

    float4 zi = ((const float4*)g_z[0])[idx];
    float4 zo = ((const float4*)g_z[1])[idx];
    float4 zc = ((const float4*)g_z[2])[idx];

    float4 cell;
    cell.x = -acc.x + tanhf(zc.x) * sigf(zi.x);
    cell.y = -acc.y + tanhf(zc.y) * sigf(zi.y);
    cell.z = -acc.z + tanhf(zc.z) * sigf(zi.z);
    cell.w = -acc.w + tanhf(zc.w) * sigf(zi.w);
    hc[(size_t)(KFR - 1) * nb4 + idx] = cell;   // last h_c_1 slice

    float4 hn;
    hn.x = tanhf(cell.x) * sigf(zo.x);
    hn.y = tanhf(cell.y) * sigf(zo.y);
    hn.z = tanhf(cell.z) * sigf(zo.z);
    hn.w = tanhf(cell.w) * sigf(zo.w);
    hid[idx] = hn;

    split4(hn, g_hid_hi + idx * 4, g_hid_lo + idx * 4);
}

// ---------------------------------------------------------------------------
extern "C" void kernel_launch(void* const* d_in, const int* in_sizes, int n_in,
                              void* d_out_v, int out_size) {
    const float* sample = (const float*)d_in[0];
    const float* hidden = (const float*)d_in[1];
    const float* cell_t = (const float*)d_in[2];
    const float* d0     = (const float*)d_in[3];
    const float* Wc     = (const float*)d_in[4];
    const float* bc     = (const float*)d_in[5];
    const float* Wi     = (const float*)d_in[6];
    const float* bi     = (const float*)d_in[7];
    const float* Wf     = (const float*)d_in[8];
    const float* bf     = (const float*)d_in[9];
    const float* Wo     = (const float*)d_in[10];
    const float* bo     = (const float*)d_in[11];
    const float* Wout   = (const float*)d_in[12];
    const float* bout   = (const float*)d_in[13];
    float* out = (float*)d_out_v;

    // one-time resources (host objects only; no device memory)
    static cudaStream_t s_copy = nullptr;
    static cudaEvent_t  e_fork = nullptr, e_join = nullptr;
    if (!s_copy) {
        cudaStreamCreateWithFlags(&s_copy, cudaStreamNonBlocking);
        cudaEventCreateWithFlags(&e_fork, cudaEventDisableTiming);
        cudaEventCreateWithFlags(&e_join, cudaEventDisableTiming);
    }

    cudaFuncSetAttribute(gates_mma_kernel,
                         cudaFuncAttributeMaxDynamicSharedMemorySize, SMEM_TOT);
    cudaFuncSetAttribute(out_mma_kernel,
                         cudaFuncAttributeMaxDynamicSharedMemorySize, SMEM_TOT);

    // 1) conversions (stream 0)
    comb_conv_kernel<<<(BB * KD / 4 + 255) / 256, 256>>>(sample, hidden, d0);
    dim3 wgrid((512 * 1536 / 4 + 255) / 256, 5);
    w_conv_kernel<<<wgrid, 256>>>(Wi, Wo, Wc, Wf, Wout);

    // fork point: copy depends on nothing but input
    cudaEventRecord(e_fork, 0);

    // 2) gates GEMM enqueued FIRST so its CTAs win the scheduler
    dim3 ggrid(4, 16, 4);
    gates_mma_kernel<<<ggrid, 256, SMEM_TOT>>>(bi, bo, bc, bf);

    // 2b) h_c_1 copy on forked stream — soaks idle DRAM under the GEMM
    cudaStreamWaitEvent(s_copy, e_fork, 0);
    hc_copy_kernel<<<1024, 256, 0, s_copy>>>(cell_t, out);

    // 3) fused elementwise + hidden_new bf16 split (stream 0)
    fused_cell_kernel<<<(BH / 4 + 255) / 256, 256>>>(cell_t, out);

    // 4) output GEMM (stream 0)
    dim3 ogrid(4, 16, 1);
    out_mma_kernel<<<ogrid, 256, SMEM_TOT>>>(bout, out);

    // join the fork back into the origin stream
    cudaEventRecord(e_join, s_copy);
    cudaStreamWaitEvent(0, e_join, 0);
}

// round 10
// speedup vs baseline: 1.5521x; 1.5521x over previous
#include <cuda_runtime.h>
#include <cuda_bf16.h>
#include <math.h>
#include <stdint.h>

#define BB   2048
#define INN  512
#define HH   512
#define KFR  32
#define OUTN 512
#define KD   1536            // IN + 2H (combined_d width)
#define KC   1024            // IN + H
#define BH   (BB*HH)

#define OFF_WI   0
#define OFF_WO   (512*1024)
#define OFF_WC   (2*512*1024)
#define OFF_WF   (3*512*1024)
#define OFF_WOUT (3*512*1024 + 512*1536)
#define W_TOTAL  (OFF_WOUT + 512*512)

// tf32 path: one 128x64 fp32 tile = 32KB; stage = A+B = 64KB; 3 stages = 192KB
#define TILE_B   32768
#define STAGE_B  (2*TILE_B)
#define NSTAGE   3
#define SMEM_TOT (NSTAGE*STAGE_B)   // 196608

// ---------------- static device scratch (tf32-rounded fp32) ----------------
__device__ float g_comb_t[BB*KD];
__device__ float g_w_t[W_TOTAL];
__device__ float g_hid_t[BH];
__device__ float g_z[4][BH];          // pre-activations: 0=i, 1=o, 2=c, 3=f

// ---------------- PTX helpers (baseline ISA only) ----------------
__device__ __forceinline__ uint32_t smem_u32(const void* p) {
    return (uint32_t)__cvta_generic_to_shared(p);
}

__device__ __forceinline__ float cvt_tf32(float x) {
    uint32_t r;
    asm("cvt.rna.tf32.f32 %0, %1;" : "=r"(r) : "f"(x));
    return __uint_as_float(r);
}

__device__ __forceinline__ void cp16(uint32_t daddr, const void* g) {
    asm volatile("cp.async.cg.shared.global [%0], [%1], 16;" :: "r"(daddr), "l"(g) : "memory");
}
#define CP_COMMIT() asm volatile("cp.async.commit_group;" ::: "memory")
template <int N>
__device__ __forceinline__ void cp_wait() {
    asm volatile("cp.async.wait_group %0;" :: "n"(N) : "memory");
}

__device__ __forceinline__ void ldsm4(uint32_t addr, uint32_t* r) {
    asm volatile("ldmatrix.sync.aligned.m8n8.x4.shared.b16 {%0,%1,%2,%3}, [%4];"
        : "=r"(r[0]), "=r"(r[1]), "=r"(r[2]), "=r"(r[3]) : "r"(addr));
}

__device__ __forceinline__ void mma_tf32(float* c, const uint32_t* a, const uint32_t* b) {
    asm volatile("mma.sync.aligned.m16n8k8.row.col.f32.tf32.tf32.f32 "
        "{%0,%1,%2,%3}, {%4,%5,%6,%7}, {%8,%9}, {%0,%1,%2,%3};"
        : "+f"(c[0]), "+f"(c[1]), "+f"(c[2]), "+f"(c[3])
        : "r"(a[0]), "r"(a[1]), "r"(a[2]), "r"(a[3]), "r"(b[0]), "r"(b[1]));
}

// ---------------------------------------------------------------------------
// cp.async loader: one K-chunk (64 fp32 cols = 256B rows) of A + B tiles.
// Per tile: 128 rows x 16 chunks(16B) = 2048 cp16 -> 8/thread; 2 tiles = 16.
// swizzle: phys_chunk = chunk ^ (row & 7)
// ---------------------------------------------------------------------------
__device__ __forceinline__ void load_stage(uint32_t sbase,
    const char* aP, const char* bP, int lda_b, int ldb_b, int k0b, int tid) {
    const char* srcs[2] = {aP, bP};
    const int lds[2] = {lda_b, ldb_b};
#pragma unroll
    for (int t = 0; t < 2; t++) {
#pragma unroll
        for (int i = 0; i < 8; i++) {
            int idx = i * 256 + tid;
            int row = idx >> 4;
            uint32_t ck = (uint32_t)(idx & 15);
            uint32_t off = (uint32_t)row * 256 + ((ck ^ ((uint32_t)row & 7)) << 4);
            cp16(sbase + t * TILE_B + off,
                 srcs[t] + (size_t)row * lds[t] + k0b + ck * 16);
        }
    }
}

// ---------------------------------------------------------------------------
// single-pass tf32 mma.sync GEMM tile: C[m,n] = sum_k A[m,k]*B[n,k] + bias[n]
// 128x128 tile, 8 warps (4Mx2N), warp tile 32x64, 3-stage pipeline.
// ---------------------------------------------------------------------------
__device__ __forceinline__ void mma_gemm_tile(
    const float* At, int lda, const float* Bt, int ldb,
    const float* __restrict__ bias, float* __restrict__ C, int ldc,
    int K, int blockM, int blockN) {
    extern __shared__ __align__(1024) char dsm[];
    const int tid  = threadIdx.x;
    const int lane = tid & 31;
    const int wid  = tid >> 5;
    const int wm   = wid & 3;    // 0..3 -> 32-row slab
    const int wn   = wid >> 2;   // 0..1 -> 64-col slab
    uint32_t sb = smem_u32(dsm);

    const int g  = lane >> 3;    // ldmatrix lane group 0..3
    const int lr = lane & 7;

    // A: matrix g -> rowoff (g&1)*8, chunkoff (g>>1)
    uint32_t aRow[2], aXor[2];
    const uint32_t aCk = (uint32_t)(g >> 1);
#pragma unroll
    for (int mt = 0; mt < 2; mt++) {
        int r = wm * 32 + mt * 16 + (g & 1) * 8 + lr;
        aRow[mt] = (uint32_t)r * 256;
        aXor[mt] = (uint32_t)r & 7;
    }
    // B: matrix g -> rowoff (g>>1)*8, chunkoff (g&1)
    uint32_t bRow[4], bXor[4];
    const uint32_t bCk = (uint32_t)(g & 1);
#pragma unroll
    for (int p = 0; p < 4; p++) {
        int r = wn * 64 + p * 16 + (g >> 1) * 8 + lr;
        bRow[p] = (uint32_t)r * 256;
        bXor[p] = (uint32_t)r & 7;
    }

    float acc[2][8][4];
#pragma unroll
    for (int mt = 0; mt < 2; mt++)
#pragma unroll
        for (int nt = 0; nt < 8; nt++)
#pragma unroll
            for (int j = 0; j < 4; j++) acc[mt][nt][j] = 0.0f;

    const char* aP = (const char*)(At + (size_t)blockM * lda);
    const char* bP = (const char*)(Bt + (size_t)blockN * ldb);
    const int lda_b = lda * 4, ldb_b = ldb * 4;
    const int NC = K / 64;

    load_stage(sb, aP, bP, lda_b, ldb_b, 0, tid);
    CP_COMMIT();
    load_stage(sb + STAGE_B, aP, bP, lda_b, ldb_b, 256, tid);
    CP_COMMIT();

    int stage = 0;
    for (int c = 0; c < NC; ++c) {
        cp_wait<1>();
        __syncthreads();
        if (c + 2 < NC) {
            int s2 = stage + 2; if (s2 >= NSTAGE) s2 -= NSTAGE;
            load_stage(sb + (uint32_t)s2 * STAGE_B, aP, bP,
                       lda_b, ldb_b, (c + 2) * 256, tid);
        }
        CP_COMMIT();

        const uint32_t st = sb + (uint32_t)stage * STAGE_B;
#pragma unroll
        for (int kk = 0; kk < 8; kk++) {
            const uint32_t ck2 = (uint32_t)(kk * 2);
            uint32_t a[2][4];
#pragma unroll
            for (int mt = 0; mt < 2; mt++) {
                uint32_t addr = st + aRow[mt] + (((ck2 + aCk) ^ aXor[mt]) << 4);
                ldsm4(addr, a[mt]);
            }
            uint32_t b[8][2];
#pragma unroll
            for (int p = 0; p < 4; p++) {
                uint32_t r[4];
                uint32_t addr = st + TILE_B + bRow[p] + (((ck2 + bCk) ^ bXor[p]) << 4);
                ldsm4(addr, r);
                b[2*p][0]   = r[0]; b[2*p][1]   = r[1];
                b[2*p+1][0] = r[2]; b[2*p+1][1] = r[3];
            }
#pragma unroll
            for (int mt = 0; mt < 2; mt++)
#pragma unroll
                for (int nt = 0; nt < 8; nt++)
                    mma_tf32(acc[mt][nt], a[mt], b[nt]);
        }
        if (++stage >= NSTAGE) stage = 0;
    }

    // epilogue: add bias, store fp32
#pragma unroll
    for (int mt = 0; mt < 2; mt++) {
        int r0 = blockM + wm * 32 + mt * 16 + (lane >> 2);
#pragma unroll
        for (int nt = 0; nt < 8; nt++) {
            int col = blockN + wn * 64 + nt * 8 + (lane & 3) * 2;
            float b0 = bias[col], b1 = bias[col + 1];
            float2 v0 = {acc[mt][nt][0] + b0, acc[mt][nt][1] + b1};
            float2 v1 = {acc[mt][nt][2] + b0, acc[mt][nt][3] + b1};
            *(float2*)(C + (size_t)r0 * ldc + col) = v0;
            *(float2*)(C + (size_t)(r0 + 8) * ldc + col) = v1;
        }
    }
}

// ---------------------------------------------------------------------------
// z order: 0 = Wf (K=1536, longest -> first), then i, o, c
__global__ __launch_bounds__(256, 1)
void gates_mma_kernel(const float* __restrict__ bi, const float* __restrict__ bo,
                      const float* __restrict__ bc, const float* __restrict__ bf) {
    int z = blockIdx.z;
    const float* wt; const float* bias; int K; float* dst;
    if      (z == 0) { wt = g_w_t + OFF_WF; bias = bf; K = KD; dst = g_z[3]; }
    else if (z == 1) { wt = g_w_t + OFF_WI; bias = bi; K = KC; dst = g_z[0]; }
    else if (z == 2) { wt = g_w_t + OFF_WO; bias = bo; K = KC; dst = g_z[1]; }
    else             { wt = g_w_t + OFF_WC; bias = bc; K = KC; dst = g_z[2]; }
    mma_gemm_tile(g_comb_t, KD, wt, K, bias, dst, HH, K,
                  blockIdx.y * 128, blockIdx.x * 128);
}

__global__ __launch_bounds__(256, 1)
void out_mma_kernel(const float* __restrict__ bout, float* __restrict__ out) {
    mma_gemm_tile(g_hid_t, HH, g_w_t + OFF_WOUT, HH,
                  bout, out, OUTN, HH, blockIdx.y * 128, blockIdx.x * 128);
}

// ---------------------------------------------------------------------------
// conversions: fp32 -> tf32-rounded fp32 (cvt.rna)
// ---------------------------------------------------------------------------
__device__ __forceinline__ float4 cvt4(float4 v) {
    return make_float4(cvt_tf32(v.x), cvt_tf32(v.y), cvt_tf32(v.z), cvt_tf32(v.w));
}

__global__ void comb_conv_kernel(const float* __restrict__ sample,
                                 const float* __restrict__ hidden,
                                 const float* __restrict__ d0) {
    int idx = blockIdx.x * blockDim.x + threadIdx.x;   // over BB*KD/4
    if (idx >= BB * KD / 4) return;
    int b  = idx / (KD / 4);
    int c4 = idx % (KD / 4);
    float4 v;
    if (c4 < INN / 4)            v = ((const float4*)sample)[b * (INN/4) + c4];
    else if (c4 < (INN+HH) / 4)  v = ((const float4*)hidden)[b * (HH/4) + (c4 - INN/4)];
    else                         v = ((const float4*)d0)[b * (HH/4) + (c4 - (INN+HH)/4)];
    ((float4*)g_comb_t)[idx] = cvt4(v);
}

__global__ void w_conv_kernel(const float* __restrict__ Wi, const float* __restrict__ Wo,
                              const float* __restrict__ Wc, const float* __restrict__ Wf,
                              const float* __restrict__ Wout) {
    int a = blockIdx.y;
    const float* src; size_t off; int n;
    if      (a == 0) { src = Wi;   off = OFF_WI;   n = 512 * 1024; }
    else if (a == 1) { src = Wo;   off = OFF_WO;   n = 512 * 1024; }
    else if (a == 2) { src = Wc;   off = OFF_WC;   n = 512 * 1024; }
    else if (a == 3) { src = Wf;   off = OFF_WF;   n = 512 * 1536; }
    else             { src = Wout; off = OFF_WOUT; n = 512 * 512;  }
    int i = blockIdx.x * blockDim.x + threadIdx.x;
    if (i * 4 >= n) return;
    float4 v = ((const float4*)src)[i];
    ((float4*)(g_w_t + off))[i] = cvt4(v);
}

// ---------------------------------------------------------------------------
// fused elementwise (R4 form: includes h_c_1 shift-copy) + tf32 hidden
// ---------------------------------------------------------------------------
__device__ __forceinline__ float sigf(float x) { return 1.0f / (1.0f + expf(-x)); }

__global__ void fused_cell_kernel(const float* __restrict__ cell_t,
                                  float* __restrict__ dout) {
    int idx = blockIdx.x * blockDim.x + threadIdx.x;   // over BH/4
    const int nb4 = BH / 4;
    if (idx >= nb4) return;

    const float4* c4  = (const float4*)cell_t;
    float4* hid = (float4*)(dout + (size_t)BB * OUTN);
    float4* hc  = (float4*)(dout + (size_t)2 * BB * OUTN);
    float4* dv  = (float4*)(dout + (size_t)2 * BB * OUTN + (size_t)KFR * BH);

    float4 zf = ((const float4*)g_z[3])[idx];
    float4 d;
    d.x = 0.5f * sigf(zf.x); d.y = 0.5f * sigf(zf.y);
    d.z = 0.5f * sigf(zf.z); d.w = 0.5f * sigf(zf.w);
    dv[idx] = d;

    float4 w   = make_float4(1.f, 1.f, 1.f, 1.f);
    float4 acc = make_float4(0.f, 0.f, 0.f, 0.f);
    float4 cv  = c4[(size_t)(KFR - 1) * nb4 + idx];
#pragma unroll
    for (int j = KFR - 1; j >= 0; j--) {
        float4 nxt;
        if (j >= 1) nxt = c4[(size_t)(j - 1) * nb4 + idx];   // prefetch next slice
        float fi  = (float)(KFR - 1 - j);
        float inv = 1.0f / (float)(KFR - j);
        w.x *= (fi - d.x) * inv;  w.y *= (fi - d.y) * inv;
        w.z *= (fi - d.z) * inv;  w.w *= (fi - d.w) * inv;
        acc.x = fmaf(w.x, cv.x, acc.x);  acc.y = fmaf(w.y, cv.y, acc.y);
        acc.z = fmaf(w.z, cv.z, acc.z);  acc.w = fmaf(w.w, cv.w, acc.w);
        if (j >= 1) { hc[(size_t)(j - 1) * nb4 + idx] = cv; cv = nxt; }
    }

    float4 zi = ((const float4*)g_z[0])[idx];
    float4 zo = ((const float4*)g_z[1])[idx];
    float4 zc = ((const float4*)g_z[2])[idx];

    float4 cell;
    cell.x = -acc.x + tanhf(zc.x) * sigf(zi.x);
    cell.y = -acc.y + tanhf(zc.y) * sigf(zi.y);
    cell.z = -acc.z + tanhf(zc.z) * sigf(zi.z);
    cell.w = -acc.w + tanhf(zc.w) * sigf(zi.w);
    hc[(size_t)(KFR - 1) * nb4 + idx] = cell;

    float4 hn;
    hn.x = tanhf(cell.x) * sigf(zo.x);
    hn.y = tanhf(cell.y) * sigf(zo.y);
    hn.z = tanhf(cell.z) * sigf(zo.z);
    hn.w = tanhf(cell.w) * sigf(zo.w);
    hid[idx] = hn;

    ((float4*)g_hid_t)[idx] = cvt4(hn);
}

// ---------------------------------------------------------------------------
extern "C" void kernel_launch(void* const* d_in, const int* in_sizes, int n_in,
                              void* d_out_v, int out_size) {
    const float* sample = (const float*)d_in[0];
    const float* hidden = (const float*)d_in[1];
    const float* cell_t = (const float*)d_in[2];
    const float* d0     = (const float*)d_in[3];
    const float* Wc     = (const float*)d_in[4];
    const float* bc     = (const float*)d_in[5];
    const float* Wi     = (const float*)d_in[6];
    const float* bi     = (const float*)d_in[7];
    const float* Wf     = (const float*)d_in[8];
    const float* bf     = (const float*)d_in[9];
    const float* Wo     = (const float*)d_in[10];
    const float* bo     = (const float*)d_in[11];
    const float* Wout   = (const float*)d_in[12];
    const float* bout   = (const float*)d_in[13];
    float* out = (float*)d_out_v;

    cudaFuncSetAttribute(gates_mma_kernel,
                         cudaFuncAttributeMaxDynamicSharedMemorySize, SMEM_TOT);
    cudaFuncSetAttribute(out_mma_kernel,
                         cudaFuncAttributeMaxDynamicSharedMemorySize, SMEM_TOT);

    // 1) tf32-round combined_d and all weights
    comb_conv_kernel<<<(BB * KD / 4 + 255) / 256, 256>>>(sample, hidden, d0);
    dim3 wgrid((512 * 1536 / 4 + 255) / 256, 5);
    w_conv_kernel<<<wgrid, 256>>>(Wi, Wo, Wc, Wf, Wout);

    // 2) 4 gate GEMMs, single-pass tf32
    dim3 ggrid(4, 16, 4);
    gates_mma_kernel<<<ggrid, 256, SMEM_TOT>>>(bi, bo, bc, bf);

    // 3) fused elementwise (incl. h_c_1 copy) + tf32 hidden
    fused_cell_kernel<<<(BH / 4 + 255) / 256, 256>>>(cell_t, out);

    // 4) output GEMM
    dim3 ogrid(4, 16, 1);
    out_mma_kernel<<<ogrid, 256, SMEM_TOT>>>(bout, out);
}

// round 11
// speedup vs baseline: 1.6461x; 1.0605x over previous
#include <cuda_runtime.h>
#include <cuda_bf16.h>
#include <math.h>
#include <stdint.h>

#define BB   2048
#define INN  512
#define HH   512
#define KFR  32
#define OUTN 512
#define KD   1536            // IN + 2H (combined_d width)
#define KC   1024            // IN + H
#define BH   (BB*HH)

#define OFF_WI   0
#define OFF_WO   (512*1024)
#define OFF_WC   (2*512*1024)
#define OFF_WF   (3*512*1024)
#define OFF_WOUT (3*512*1024 + 512*1536)
#define W_TOTAL  (OFF_WOUT + 512*512)

// tf32 path, K-chunk 32 fp32: one 128x32 tile = 16KB; stage = A+B = 32KB;
// 3 stages = 96KB -> 2 CTAs/SM (single wave for the 256-CTA gates grid)
#define TILE_B   16384
#define STAGE_B  (2*TILE_B)
#define NSTAGE   3
#define SMEM_TOT (NSTAGE*STAGE_B)   // 98304

// ---------------- static device scratch (tf32-rounded fp32) ----------------
__device__ float g_comb_t[BB*KD];
__device__ float g_w_t[W_TOTAL];
__device__ float g_hid_t[BH];
__device__ float g_z[4][BH];          // pre-activations: 0=i, 1=o, 2=c, 3=f

// ---------------- PTX helpers (baseline ISA only) ----------------
__device__ __forceinline__ uint32_t smem_u32(const void* p) {
    return (uint32_t)__cvta_generic_to_shared(p);
}

__device__ __forceinline__ float cvt_tf32(float x) {
    uint32_t r;
    asm("cvt.rna.tf32.f32 %0, %1;" : "=r"(r) : "f"(x));
    return __uint_as_float(r);
}

__device__ __forceinline__ void cp16(uint32_t daddr, const void* g) {
    asm volatile("cp.async.cg.shared.global [%0], [%1], 16;" :: "r"(daddr), "l"(g) : "memory");
}
#define CP_COMMIT() asm volatile("cp.async.commit_group;" ::: "memory")
template <int N>
__device__ __forceinline__ void cp_wait() {
    asm volatile("cp.async.wait_group %0;" :: "n"(N) : "memory");
}

__device__ __forceinline__ void ldsm4(uint32_t addr, uint32_t* r) {
    asm volatile("ldmatrix.sync.aligned.m8n8.x4.shared.b16 {%0,%1,%2,%3}, [%4];"
        : "=r"(r[0]), "=r"(r[1]), "=r"(r[2]), "=r"(r[3]) : "r"(addr));
}

__device__ __forceinline__ void mma_tf32(float* c, const uint32_t* a, const uint32_t* b) {
    asm volatile("mma.sync.aligned.m16n8k8.row.col.f32.tf32.tf32.f32 "
        "{%0,%1,%2,%3}, {%4,%5,%6,%7}, {%8,%9}, {%0,%1,%2,%3};"
        : "+f"(c[0]), "+f"(c[1]), "+f"(c[2]), "+f"(c[3])
        : "r"(a[0]), "r"(a[1]), "r"(a[2]), "r"(a[3]), "r"(b[0]), "r"(b[1]));
}

// ---------------------------------------------------------------------------
// cp.async loader: one K-chunk (32 fp32 cols = 128B rows) of A + B tiles.
// Per tile: 128 rows x 8 chunks(16B) = 1024 cp16 -> 4/thread; 2 tiles = 8.
// swizzle: phys_chunk = chunk ^ (row & 7)
// ---------------------------------------------------------------------------
__device__ __forceinline__ void load_stage(uint32_t sbase,
    const char* aP, const char* bP, int lda_b, int ldb_b, int k0b, int tid) {
    const char* srcs[2] = {aP, bP};
    const int lds[2] = {lda_b, ldb_b};
#pragma unroll
    for (int t = 0; t < 2; t++) {
#pragma unroll
        for (int i = 0; i < 4; i++) {
            int idx = i * 256 + tid;
            int row = idx >> 3;
            uint32_t ck = (uint32_t)(idx & 7);
            uint32_t off = (uint32_t)row * 128 + ((ck ^ ((uint32_t)row & 7)) << 4);
            cp16(sbase + t * TILE_B + off,
                 srcs[t] + (size_t)row * lds[t] + k0b + ck * 16);
        }
    }
}

// ---------------------------------------------------------------------------
// single-pass tf32 mma.sync GEMM tile: C[m,n] = sum_k A[m,k]*B[n,k] + bias[n]
// 128x128 tile, 8 warps (4Mx2N), warp tile 32x64, 3-stage, 2 CTAs/SM.
// ---------------------------------------------------------------------------
__device__ __forceinline__ void mma_gemm_tile(
    const float* At, int lda, const float* Bt, int ldb,
    const float* __restrict__ bias, float* __restrict__ C, int ldc,
    int K, int blockM, int blockN) {
    extern __shared__ __align__(1024) char dsm[];
    const int tid  = threadIdx.x;
    const int lane = tid & 31;
    const int wid  = tid >> 5;
    const int wm   = wid & 3;    // 0..3 -> 32-row slab
    const int wn   = wid >> 2;   // 0..1 -> 64-col slab
    uint32_t sb = smem_u32(dsm);

    const int g  = lane >> 3;    // ldmatrix lane group 0..3
    const int lr = lane & 7;

    // A: matrix g -> rowoff (g&1)*8, chunkoff (g>>1)
    uint32_t aRow[2], aXor[2];
    const uint32_t aCk = (uint32_t)(g >> 1);
#pragma unroll
    for (int mt = 0; mt < 2; mt++) {
        int r = wm * 32 + mt * 16 + (g & 1) * 8 + lr;
        aRow[mt] = (uint32_t)r * 128;
        aXor[mt] = (uint32_t)r & 7;
    }
    // B: matrix g -> rowoff (g>>1)*8, chunkoff (g&1)
    uint32_t bRow[4], bXor[4];
    const uint32_t bCk = (uint32_t)(g & 1);
#pragma unroll
    for (int p = 0; p < 4; p++) {
        int r = wn * 64 + p * 16 + (g >> 1) * 8 + lr;
        bRow[p] = (uint32_t)r * 128;
        bXor[p] = (uint32_t)r & 7;
    }

    float acc[2][8][4];
#pragma unroll
    for (int mt = 0; mt < 2; mt++)
#pragma unroll
        for (int nt = 0; nt < 8; nt++)
#pragma unroll
            for (int j = 0; j < 4; j++) acc[mt][nt][j] = 0.0f;

    const char* aP = (const char*)(At + (size_t)blockM * lda);
    const char* bP = (const char*)(Bt + (size_t)blockN * ldb);
    const int lda_b = lda * 4, ldb_b = ldb * 4;
    const int NC = K / 32;

    load_stage(sb, aP, bP, lda_b, ldb_b, 0, tid);
    CP_COMMIT();
    load_stage(sb + STAGE_B, aP, bP, lda_b, ldb_b, 128, tid);
    CP_COMMIT();

    int stage = 0;
    for (int c = 0; c < NC; ++c) {
        cp_wait<1>();
        __syncthreads();
        if (c + 2 < NC) {
            int s2 = stage + 2; if (s2 >= NSTAGE) s2 -= NSTAGE;
            load_stage(sb + (uint32_t)s2 * STAGE_B, aP, bP,
                       lda_b, ldb_b, (c + 2) * 128, tid);
        }
        CP_COMMIT();

        const uint32_t st = sb + (uint32_t)stage * STAGE_B;
#pragma unroll
        for (int kk = 0; kk < 4; kk++) {
            const uint32_t ck2 = (uint32_t)(kk * 2);
            uint32_t a[2][4];
#pragma unroll
            for (int mt = 0; mt < 2; mt++) {
                uint32_t addr = st + aRow[mt] + (((ck2 + aCk) ^ aXor[mt]) << 4);
                ldsm4(addr, a[mt]);
            }
            uint32_t b[8][2];
#pragma unroll
            for (int p = 0; p < 4; p++) {
                uint32_t r[4];
                uint32_t addr = st + TILE_B + bRow[p] + (((ck2 + bCk) ^ bXor[p]) << 4);
                ldsm4(addr, r);
                b[2*p][0]   = r[0]; b[2*p][1]   = r[1];
                b[2*p+1][0] = r[2]; b[2*p+1][1] = r[3];
            }
#pragma unroll
            for (int mt = 0; mt < 2; mt++)
#pragma unroll
                for (int nt = 0; nt < 8; nt++)
                    mma_tf32(acc[mt][nt], a[mt], b[nt]);
        }
        if (++stage >= NSTAGE) stage = 0;
    }

    // epilogue: add bias, store fp32
#pragma unroll
    for (int mt = 0; mt < 2; mt++) {
        int r0 = blockM + wm * 32 + mt * 16 + (lane >> 2);
#pragma unroll
        for (int nt = 0; nt < 8; nt++) {
            int col = blockN + wn * 64 + nt * 8 + (lane & 3) * 2;
            float b0 = bias[col], b1 = bias[col + 1];
            float2 v0 = {acc[mt][nt][0] + b0, acc[mt][nt][1] + b1};
            float2 v1 = {acc[mt][nt][2] + b0, acc[mt][nt][3] + b1};
            *(float2*)(C + (size_t)r0 * ldc + col) = v0;
            *(float2*)(C + (size_t)(r0 + 8) * ldc + col) = v1;
        }
    }
}

// ---------------------------------------------------------------------------
// z order: 0 = Wf (K=1536, longest -> first), then i, o, c
__global__ __launch_bounds__(256, 2)
void gates_mma_kernel(const float* __restrict__ bi, const float* __restrict__ bo,
                      const float* __restrict__ bc, const float* __restrict__ bf) {
    int z = blockIdx.z;
    const float* wt; const float* bias; int K; float* dst;
    if      (z == 0) { wt = g_w_t + OFF_WF; bias = bf; K = KD; dst = g_z[3]; }
    else if (z == 1) { wt = g_w_t + OFF_WI; bias = bi; K = KC; dst = g_z[0]; }
    else if (z == 2) { wt = g_w_t + OFF_WO; bias = bo; K = KC; dst = g_z[1]; }
    else             { wt = g_w_t + OFF_WC; bias = bc; K = KC; dst = g_z[2]; }
    mma_gemm_tile(g_comb_t, KD, wt, K, bias, dst, HH, K,
                  blockIdx.y * 128, blockIdx.x * 128);
}

__global__ __launch_bounds__(256, 2)
void out_mma_kernel(const float* __restrict__ bout, float* __restrict__ out) {
    mma_gemm_tile(g_hid_t, HH, g_w_t + OFF_WOUT, HH,
                  bout, out, OUTN, HH, blockIdx.y * 128, blockIdx.x * 128);
}

// ---------------------------------------------------------------------------
// conversions: fp32 -> tf32-rounded fp32 (cvt.rna)
// ---------------------------------------------------------------------------
__device__ __forceinline__ float4 cvt4(float4 v) {
    return make_float4(cvt_tf32(v.x), cvt_tf32(v.y), cvt_tf32(v.z), cvt_tf32(v.w));
}

__global__ void comb_conv_kernel(const float* __restrict__ sample,
                                 const float* __restrict__ hidden,
                                 const float* __restrict__ d0) {
    int idx = blockIdx.x * blockDim.x + threadIdx.x;   // over BB*KD/4
    if (idx >= BB * KD / 4) return;
    int b  = idx / (KD / 4);
    int c4 = idx % (KD / 4);
    float4 v;
    if (c4 < INN / 4)            v = ((const float4*)sample)[b * (INN/4) + c4];
    else if (c4 < (INN+HH) / 4)  v = ((const float4*)hidden)[b * (HH/4) + (c4 - INN/4)];
    else                         v = ((const float4*)d0)[b * (HH/4) + (c4 - (INN+HH)/4)];
    ((float4*)g_comb_t)[idx] = cvt4(v);
}

__global__ void w_conv_kernel(const float* __restrict__ Wi, const float* __restrict__ Wo,
                              const float* __restrict__ Wc, const float* __restrict__ Wf,
                              const float* __restrict__ Wout) {
    int a = blockIdx.y;
    const float* src; size_t off; int n;
    if      (a == 0) { src = Wi;   off = OFF_WI;   n = 512 * 1024; }
    else if (a == 1) { src = Wo;   off = OFF_WO;   n = 512 * 1024; }
    else if (a == 2) { src = Wc;   off = OFF_WC;   n = 512 * 1024; }
    else if (a == 3) { src = Wf;   off = OFF_WF;   n = 512 * 1536; }
    else             { src = Wout; off = OFF_WOUT; n = 512 * 512;  }
    int i = blockIdx.x * blockDim.x + threadIdx.x;
    if (i * 4 >= n) return;
    float4 v = ((const float4*)src)[i];
    ((float4*)(g_w_t + off))[i] = cvt4(v);
}

// ---------------------------------------------------------------------------
// fused elementwise (incl. h_c_1 shift-copy) + tf32 hidden
// ---------------------------------------------------------------------------
__device__ __forceinline__ float sigf(float x) { return 1.0f / (1.0f + expf(-x)); }

__global__ void fused_cell_kernel(const float* __restrict__ cell_t,
                                  float* __restrict__ dout) {
    int idx = blockIdx.x * blockDim.x + threadIdx.x;   // over BH/4
    const int nb4 = BH / 4;
    if (idx >= nb4) return;

    const float4* c4  = (const float4*)cell_t;
    float4* hid = (float4*)(dout + (size_t)BB * OUTN);
    float4* hc  = (float4*)(dout + (size_t)2 * BB * OUTN);
    float4* dv  = (float4*)(dout + (size_t)2 * BB * OUTN + (size_t)KFR * BH);

    float4 zf = ((const float4*)g_z[3])[idx];
    float4 d;
    d.x = 0.5f * sigf(zf.x); d.y = 0.5f * sigf(zf.y);
    d.z = 0.5f * sigf(zf.z); d.w = 0.5f * sigf(zf.w);
    dv[idx] = d;

    float4 w   = make_float4(1.f, 1.f, 1.f, 1.f);
    float4 acc = make_float4(0.f, 0.f, 0.f, 0.f);
    float4 cv  = c4[(size_t)(KFR - 1) * nb4 + idx];
#pragma unroll
    for (int j = KFR - 1; j >= 0; j--) {
        float4 nxt;
        if (j >= 1) nxt = c4[(size_t)(j - 1) * nb4 + idx];   // prefetch next slice
        float fi  = (float)(KFR - 1 - j);
        float inv = 1.0f / (float)(KFR - j);
        w.x *= (fi - d.x) * inv;  w.y *= (fi - d.y) * inv;
        w.z *= (fi - d.z) * inv;  w.w *= (fi - d.w) * inv;
        acc.x = fmaf(w.x, cv.x, acc.x);  acc.y = fmaf(w.y, cv.y, acc.y);
        acc.z = fmaf(w.z, cv.z, acc.z);  acc.w = fmaf(w.w, cv.w, acc.w);
        if (j >= 1) { hc[(size_t)(j - 1) * nb4 + idx] = cv; cv = nxt; }
    }

    float4 zi = ((const float4*)g_z[0])[idx];
    float4 zo = ((const float4*)g_z[1])[idx];
    float4 zc = ((const float4*)g_z[2])[idx];

    float4 cell;
    cell.x = -acc.x + tanhf(zc.x) * sigf(zi.x);
    cell.y = -acc.y + tanhf(zc.y) * sigf(zi.y);
    cell.z = -acc.z + tanhf(zc.z) * sigf(zi.z);
    cell.w = -acc.w + tanhf(zc.w) * sigf(zi.w);
    hc[(size_t)(KFR - 1) * nb4 + idx] = cell;

    float4 hn;
    hn.x = tanhf(cell.x) * sigf(zo.x);
    hn.y = tanhf(cell.y) * sigf(zo.y);
    hn.z = tanhf(cell.z) * sigf(zo.z);
    hn.w = tanhf(cell.w) * sigf(zo.w);
    hid[idx] = hn;

    ((float4*)g_hid_t)[idx] = cvt4(hn);
}

// ---------------------------------------------------------------------------
extern "C" void kernel_launch(void* const* d_in, const int* in_sizes, int n_in,
                              void* d_out_v, int out_size) {
    const float* sample = (const float*)d_in[0];
    const float* hidden = (const float*)d_in[1];
    const float* cell_t = (const float*)d_in[2];
    const float* d0     = (const float*)d_in[3];
    const float* Wc     = (const float*)d_in[4];
    const float* bc     = (const float*)d_in[5];
    const float* Wi     = (const float*)d_in[6];
    const float* bi     = (const float*)d_in[7];
    const float* Wf     = (const float*)d_in[8];
    const float* bf     = (const float*)d_in[9];
    const float* Wo     = (const float*)d_in[10];
    const float* bo     = (const float*)d_in[11];
    const float* Wout   = (const float*)d_in[12];
    const float* bout   = (const float*)d_in[13];
    float* out = (float*)d_out_v;

    cudaFuncSetAttribute(gates_mma_kernel,
                         cudaFuncAttributeMaxDynamicSharedMemorySize, SMEM_TOT);
    cudaFuncSetAttribute(out_mma_kernel,
                         cudaFuncAttributeMaxDynamicSharedMemorySize, SMEM_TOT);

    // 1) tf32-round combined_d and all weights
    comb_conv_kernel<<<(BB * KD / 4 + 255) / 256, 256>>>(sample, hidden, d0);
    dim3 wgrid((512 * 1536 / 4 + 255) / 256, 5);
    w_conv_kernel<<<wgrid, 256>>>(Wi, Wo, Wc, Wf, Wout);

    // 2) 4 gate GEMMs, single-pass tf32, 2 CTAs/SM -> single wave
    dim3 ggrid(4, 16, 4);
    gates_mma_kernel<<<ggrid, 256, SMEM_TOT>>>(bi, bo, bc, bf);

    // 3) fused elementwise (incl. h_c_1 copy) + tf32 hidden
    fused_cell_kernel<<<(BH / 4 + 255) / 256, 256>>>(cell_t, out);

    // 4) output GEMM
    dim3 ogrid(4, 16, 1);
    out_mma_kernel<<<ogrid, 256, SMEM_TOT>>>(bout, out);
}

// round 12
// speedup vs baseline: 2.1832x; 1.3263x over previous
#include <cuda_runtime.h>
#include <cuda_fp16.h>
#include <math.h>
#include <stdint.h>

#define BB   2048
#define INN  512
#define HH   512
#define KFR  32
#define OUTN 512
#define KD   1536            // IN + 2H (combined_d width)
#define KC   1024            // IN + H
#define BH   (BB*HH)

#define OFF_WI   0
#define OFF_WO   (512*1024)
#define OFF_WC   (2*512*1024)
#define OFF_WF   (3*512*1024)
#define OFF_WOUT (3*512*1024 + 512*1536)
#define W_TOTAL  (OFF_WOUT + 512*512)

// fp16 single-pass: one 128x64 fp16 tile = 16KB; stage = A+B = 32KB;
// 3 stages = 96KB -> 2 CTAs/SM (single wave for the 256-CTA gates grid)
#define TILE_B   16384
#define STAGE_B  (2*TILE_B)
#define NSTAGE   3
#define SMEM_TOT (NSTAGE*STAGE_B)   // 98304

// ---------------- static device scratch (fp16) ----------------
__device__ __half g_comb_h[BB*KD];
__device__ __half g_w_h[W_TOTAL];
__device__ __half g_hid_h[BH];
__device__ float g_z[4][BH];          // pre-activations: 0=i, 1=o, 2=c, 3=f

// ---------------- PTX helpers (baseline ISA only) ----------------
__device__ __forceinline__ uint32_t smem_u32(const void* p) {
    return (uint32_t)__cvta_generic_to_shared(p);
}

__device__ __forceinline__ void cp16(uint32_t daddr, const void* g) {
    asm volatile("cp.async.cg.shared.global [%0], [%1], 16;" :: "r"(daddr), "l"(g) : "memory");
}
#define CP_COMMIT() asm volatile("cp.async.commit_group;" ::: "memory")
template <int N>
__device__ __forceinline__ void cp_wait() {
    asm volatile("cp.async.wait_group %0;" :: "n"(N) : "memory");
}

__device__ __forceinline__ void ldsm4(uint32_t addr, uint32_t* r) {
    asm volatile("ldmatrix.sync.aligned.m8n8.x4.shared.b16 {%0,%1,%2,%3}, [%4];"
        : "=r"(r[0]), "=r"(r[1]), "=r"(r[2]), "=r"(r[3]) : "r"(addr));
}

__device__ __forceinline__ void mma_fp16(float* c, const uint32_t* a, const uint32_t* b) {
    asm volatile("mma.sync.aligned.m16n8k16.row.col.f32.f16.f16.f32 "
        "{%0,%1,%2,%3}, {%4,%5,%6,%7}, {%8,%9}, {%0,%1,%2,%3};"
        : "+f"(c[0]), "+f"(c[1]), "+f"(c[2]), "+f"(c[3])
        : "r"(a[0]), "r"(a[1]), "r"(a[2]), "r"(a[3]), "r"(b[0]), "r"(b[1]));
}

// ---------------------------------------------------------------------------
// cp.async loader: one K-chunk (64 fp16 cols = 128B rows) of A + B tiles.
// Per tile: 128 rows x 8 chunks(16B) = 1024 cp16 -> 4/thread; 2 tiles = 8.
// swizzle: phys_col16 = col16 ^ (row & 7)
// ---------------------------------------------------------------------------
__device__ __forceinline__ void load_stage(uint32_t sbase,
    const char* aP, const char* bP, int lda_b, int ldb_b, int k0b, int tid) {
    const char* srcs[2] = {aP, bP};
    const int lds[2] = {lda_b, ldb_b};
#pragma unroll
    for (int t = 0; t < 2; t++) {
#pragma unroll
        for (int i = 0; i < 4; i++) {
            int idx = i * 256 + tid;
            int row = idx >> 3;
            uint32_t ch = (uint32_t)(idx & 7) * 16;
            uint32_t off = (uint32_t)row * 128 + (ch ^ (((uint32_t)row & 7) << 4));
            cp16(sbase + t * TILE_B + off,
                 srcs[t] + (size_t)row * lds[t] + k0b + ch);
        }
    }
}

// ---------------------------------------------------------------------------
// single-pass fp16 mma.sync GEMM tile: C[m,n] = sum_k A[m,k]*B[n,k] + bias[n]
// 128x128 tile, 8 warps (4Mx2N), warp tile 32x64, 3-stage, 2 CTAs/SM.
// ---------------------------------------------------------------------------
__device__ __forceinline__ void mma_gemm_tile(
    const __half* Ah, int lda, const __half* Bh, int ldb,
    const float* __restrict__ bias, float* __restrict__ C, int ldc,
    int K, int blockM, int blockN) {
    extern __shared__ __align__(1024) char dsm[];
    const int tid  = threadIdx.x;
    const int lane = tid & 31;
    const int wid  = tid >> 5;
    const int wm   = wid & 3;    // 0..3 -> 32-row slab
    const int wn   = wid >> 2;   // 0..1 -> 64-col slab
    uint32_t sb = smem_u32(dsm);

    const uint32_t a_kb = ((uint32_t)lane >> 4) * 16;          // 0/16
    const uint32_t b_kb = (((uint32_t)lane >> 3) & 1) * 16;    // 0/16
    uint32_t aRow[2], aXor[2];
#pragma unroll
    for (int mt = 0; mt < 2; mt++) {
        int r = wm * 32 + mt * 16 + (lane & 15);
        aRow[mt] = (uint32_t)r * 128;
        aXor[mt] = ((uint32_t)r & 7) << 4;
    }
    uint32_t bRow[4], bXor[4];
#pragma unroll
    for (int g = 0; g < 4; g++) {
        int r = wn * 64 + g * 16 + (((lane >> 4) << 3) + (lane & 7));
        bRow[g] = (uint32_t)r * 128;
        bXor[g] = ((uint32_t)r & 7) << 4;
    }

    float acc[2][8][4];
#pragma unroll
    for (int mt = 0; mt < 2; mt++)
#pragma unroll
        for (int nt = 0; nt < 8; nt++)
#pragma unroll
            for (int j = 0; j < 4; j++) acc[mt][nt][j] = 0.0f;

    const char* aP = (const char*)(Ah + (size_t)blockM * lda);
    const char* bP = (const char*)(Bh + (size_t)blockN * ldb);
    const int lda_b = lda * 2, ldb_b = ldb * 2;
    const int NC = K / 64;

    load_stage(sb, aP, bP, lda_b, ldb_b, 0, tid);
    CP_COMMIT();
    load_stage(sb + STAGE_B, aP, bP, lda_b, ldb_b, 128, tid);
    CP_COMMIT();

    int stage = 0;
    for (int c = 0; c < NC; ++c) {
        cp_wait<1>();
        __syncthreads();
        if (c + 2 < NC) {
            int s2 = stage + 2; if (s2 >= NSTAGE) s2 -= NSTAGE;
            load_stage(sb + (uint32_t)s2 * STAGE_B, aP, bP,
                       lda_b, ldb_b, (c + 2) * 128, tid);
        }
        CP_COMMIT();

        const uint32_t st = sb + (uint32_t)stage * STAGE_B;
#pragma unroll
        for (int kk = 0; kk < 4; kk++) {
            uint32_t a[2][4];
#pragma unroll
            for (int mt = 0; mt < 2; mt++) {
                uint32_t col = ((uint32_t)(kk * 32) + a_kb) ^ aXor[mt];
                ldsm4(st + aRow[mt] + col, a[mt]);
            }
            uint32_t b[8][2];
#pragma unroll
            for (int g = 0; g < 4; g++) {
                uint32_t col = ((uint32_t)(kk * 32) + b_kb) ^ bXor[g];
                uint32_t r[4];
                ldsm4(st + TILE_B + bRow[g] + col, r);
                b[2*g][0]   = r[0]; b[2*g][1]   = r[1];
                b[2*g+1][0] = r[2]; b[2*g+1][1] = r[3];
            }
#pragma unroll
            for (int mt = 0; mt < 2; mt++)
#pragma unroll
                for (int nt = 0; nt < 8; nt++)
                    mma_fp16(acc[mt][nt], a[mt], b[nt]);
        }
        if (++stage >= NSTAGE) stage = 0;
    }

    // epilogue: add bias, store fp32
#pragma unroll
    for (int mt = 0; mt < 2; mt++) {
        int r0 = blockM + wm * 32 + mt * 16 + (lane >> 2);
#pragma unroll
        for (int nt = 0; nt < 8; nt++) {
            int col = blockN + wn * 64 + nt * 8 + (lane & 3) * 2;
            float b0 = bias[col], b1 = bias[col + 1];
            float2 v0 = {acc[mt][nt][0] + b0, acc[mt][nt][1] + b1};
            float2 v1 = {acc[mt][nt][2] + b0, acc[mt][nt][3] + b1};
            *(float2*)(C + (size_t)r0 * ldc + col) = v0;
            *(float2*)(C + (size_t)(r0 + 8) * ldc + col) = v1;
        }
    }
}

// ---------------------------------------------------------------------------
// z order: 0 = Wf (K=1536, longest -> first), then i, o, c
__global__ __launch_bounds__(256, 2)
void gates_mma_kernel(const float* __restrict__ bi, const float* __restrict__ bo,
                      const float* __restrict__ bc, const float* __restrict__ bf) {
    int z = blockIdx.z;
    const __half* wt; const float* bias; int K; float* dst;
    if      (z == 0) { wt = g_w_h + OFF_WF; bias = bf; K = KD; dst = g_z[3]; }
    else if (z == 1) { wt = g_w_h + OFF_WI; bias = bi; K = KC; dst = g_z[0]; }
    else if (z == 2) { wt = g_w_h + OFF_WO; bias = bo; K = KC; dst = g_z[1]; }
    else             { wt = g_w_h + OFF_WC; bias = bc; K = KC; dst = g_z[2]; }
    mma_gemm_tile(g_comb_h, KD, wt, K, bias, dst, HH, K,
                  blockIdx.y * 128, blockIdx.x * 128);
}

__global__ __launch_bounds__(256, 2)
void out_mma_kernel(const float* __restrict__ bout, float* __restrict__ out) {
    mma_gemm_tile(g_hid_h, HH, g_w_h + OFF_WOUT, HH,
                  bout, out, OUTN, HH, blockIdx.y * 128, blockIdx.x * 128);
}

// ---------------------------------------------------------------------------
// conversions: fp32 -> fp16
// ---------------------------------------------------------------------------
__device__ __forceinline__ void cvt4h(float4 v, __half* dst) {
    union { __half h[4]; uint2 u; } H;
    H.h[0] = __float2half_rn(v.x);
    H.h[1] = __float2half_rn(v.y);
    H.h[2] = __float2half_rn(v.z);
    H.h[3] = __float2half_rn(v.w);
    *(uint2*)dst = H.u;
}

__global__ void comb_conv_kernel(const float* __restrict__ sample,
                                 const float* __restrict__ hidden,
                                 const float* __restrict__ d0) {
    int idx = blockIdx.x * blockDim.x + threadIdx.x;   // over BB*KD/4
    if (idx >= BB * KD / 4) return;
    int b  = idx / (KD / 4);
    int c4 = idx % (KD / 4);
    float4 v;
    if (c4 < INN / 4)            v = ((const float4*)sample)[b * (INN/4) + c4];
    else if (c4 < (INN+HH) / 4)  v = ((const float4*)hidden)[b * (HH/4) + (c4 - INN/4)];
    else                         v = ((const float4*)d0)[b * (HH/4) + (c4 - (INN+HH)/4)];
    cvt4h(v, g_comb_h + (size_t)idx * 4);
}

__global__ void w_conv_kernel(const float* __restrict__ Wi, const float* __restrict__ Wo,
                              const float* __restrict__ Wc, const float* __restrict__ Wf,
                              const float* __restrict__ Wout) {
    int a = blockIdx.y;
    const float* src; size_t off; int n;
    if      (a == 0) { src = Wi;   off = OFF_WI;   n = 512 * 1024; }
    else if (a == 1) { src = Wo;   off = OFF_WO;   n = 512 * 1024; }
    else if (a == 2) { src = Wc;   off = OFF_WC;   n = 512 * 1024; }
    else if (a == 3) { src = Wf;   off = OFF_WF;   n = 512 * 1536; }
    else             { src = Wout; off = OFF_WOUT; n = 512 * 512;  }
    int i = blockIdx.x * blockDim.x + threadIdx.x;
    if (i * 4 >= n) return;
    float4 v = ((const float4*)src)[i];
    cvt4h(v, g_w_h + off + (size_t)i * 4);
}

// ---------------------------------------------------------------------------
// fused elementwise (incl. h_c_1 shift-copy) + fp16 hidden
// ---------------------------------------------------------------------------
__device__ __forceinline__ float sigf(float x) { return 1.0f / (1.0f + expf(-x)); }

__global__ void fused_cell_kernel(const float* __restrict__ cell_t,
                                  float* __restrict__ dout) {
    int idx = blockIdx.x * blockDim.x + threadIdx.x;   // over BH/4
    const int nb4 = BH / 4;
    if (idx >= nb4) return;

    const float4* c4  = (const float4*)cell_t;
    float4* hid = (float4*)(dout + (size_t)BB * OUTN);
    float4* hc  = (float4*)(dout + (size_t)2 * BB * OUTN);
    float4* dv  = (float4*)(dout + (size_t)2 * BB * OUTN + (size_t)KFR * BH);

    float4 zf = ((const float4*)g_z[3])[idx];
    float4 d;
    d.x = 0.5f * sigf(zf.x); d.y = 0.5f * sigf(zf.y);
    d.z = 0.5f * sigf(zf.z); d.w = 0.5f * sigf(zf.w);
    dv[idx] = d;

    float4 w   = make_float4(1.f, 1.f, 1.f, 1.f);
    float4 acc = make_float4(0.f, 0.f, 0.f, 0.f);
    float4 cv  = c4[(size_t)(KFR - 1) * nb4 + idx];
#pragma unroll
    for (int j = KFR - 1; j >= 0; j--) {
        float4 nxt;
        if (j >= 1) nxt = c4[(size_t)(j - 1) * nb4 + idx];   // prefetch next slice
        float fi  = (float)(KFR - 1 - j);
        float inv = 1.0f / (float)(KFR - j);
        w.x *= (fi - d.x) * inv;  w.y *= (fi - d.y) * inv;
        w.z *= (fi - d.z) * inv;  w.w *= (fi - d.w) * inv;
        acc.x = fmaf(w.x, cv.x, acc.x);  acc.y = fmaf(w.y, cv.y, acc.y);
        acc.z = fmaf(w.z, cv.z, acc.z);  acc.w = fmaf(w.w, cv.w, acc.w);
        if (j >= 1) { hc[(size_t)(j - 1) * nb4 + idx] = cv; cv = nxt; }
    }

    float4 zi = ((const float4*)g_z[0])[idx];
    float4 zo = ((const float4*)g_z[1])[idx];
    float4 zc = ((const float4*)g_z[2])[idx];

    float4 cell;
    cell.x = -acc.x + tanhf(zc.x) * sigf(zi.x);
    cell.y = -acc.y + tanhf(zc.y) * sigf(zi.y);
    cell.z = -acc.z + tanhf(zc.z) * sigf(zi.z);
    cell.w = -acc.w + tanhf(zc.w) * sigf(zi.w);
    hc[(size_t)(KFR - 1) * nb4 + idx] = cell;

    float4 hn;
    hn.x = tanhf(cell.x) * sigf(zo.x);
    hn.y = tanhf(cell.y) * sigf(zo.y);
    hn.z = tanhf(cell.z) * sigf(zo.z);
    hn.w = tanhf(cell.w) * sigf(zo.w);
    hid[idx] = hn;

    cvt4h(hn, g_hid_h + (size_t)idx * 4);
}

// ---------------------------------------------------------------------------
extern "C" void kernel_launch(void* const* d_in, const int* in_sizes, int n_in,
                              void* d_out_v, int out_size) {
    const float* sample = (const float*)d_in[0];
    const float* hidden = (const float*)d_in[1];
    const float* cell_t = (const float*)d_in[2];
    const float* d0     = (const float*)d_in[3];
    const float* Wc     = (const float*)d_in[4];
    const float* bc     = (const float*)d_in[5];
    const float* Wi     = (const float*)d_in[6];
    const float* bi     = (const float*)d_in[7];
    const float* Wf     = (const float*)d_in[8];
    const float* bf     = (const float*)d_in[9];
    const float* Wo     = (const float*)d_in[10];
    const float* bo     = (const float*)d_in[11];
    const float* Wout   = (const float*)d_in[12];
    const float* bout   = (const float*)d_in[13];
    float* out = (float*)d_out_v;

    cudaFuncSetAttribute(gates_mma_kernel,
                         cudaFuncAttributeMaxDynamicSharedMemorySize, SMEM_TOT);
    cudaFuncSetAttribute(out_mma_kernel,
                         cudaFuncAttributeMaxDynamicSharedMemorySize, SMEM_TOT);

    // 1) fp16 conversions of combined_d and all weights
    comb_conv_kernel<<<(BB * KD / 4 + 255) / 256, 256>>>(sample, hidden, d0);
    dim3 wgrid((512 * 1536 / 4 + 255) / 256, 5);
    w_conv_kernel<<<wgrid, 256>>>(Wi, Wo, Wc, Wf, Wout);

    // 2) 4 gate GEMMs, single-pass fp16, 2 CTAs/SM -> single wave
    dim3 ggrid(4, 16, 4);
    gates_mma_kernel<<<ggrid, 256, SMEM_TOT>>>(bi, bo, bc, bf);

    // 3) fused elementwise (incl. h_c_1 copy) + fp16 hidden
    fused_cell_kernel<<<(BH / 4 + 255) / 256, 256>>>(cell_t, out);

    // 4) output GEMM
    dim3 ogrid(4, 16, 1);
    out_mma_kernel<<<ogrid, 256, SMEM_TOT>>>(bout, out);
}

// round 13
// speedup vs baseline: 2.3665x; 1.0839x over previous
#include <cuda_runtime.h>
#include <cuda_fp16.h>
#include <math.h>
#include <stdint.h>

#define BB   2048
#define INN  512
#define HH   512
#define KFR  32
#define OUTN 512
#define KD   1536            // IN + 2H (combined_d width)
#define KC   1024            // IN + H
#define BH   (BB*HH)

#define OFF_WI   0
#define OFF_WO   (512*1024)
#define OFF_WC   (2*512*1024)
#define OFF_WF   (3*512*1024)
#define OFF_WOUT (3*512*1024 + 512*1536)
#define W_TOTAL  (OFF_WOUT + 512*512)

// fp16 single-pass: one 128x64 fp16 tile = 16KB; stage = A+B = 32KB;
// 3 stages = 96KB -> 2 CTAs/SM (single wave for the 256-CTA gates grid)
#define TILE_B   16384
#define STAGE_B  (2*TILE_B)
#define NSTAGE   3
#define SMEM_TOT (NSTAGE*STAGE_B)   // 98304

// flat conversion index ranges (float4 units)
#define CVF4_COMB  (BB*KD/4)                    // 786432
#define CVF4_W1    (512*1024/4)                 // 131072 (Wi/Wo/Wc each)
#define CVF4_WF    (512*1536/4)                 // 196608
#define CVF4_WOUT  (512*512/4)                  // 65536
#define CVF4_TOTAL (CVF4_COMB + 3*CVF4_W1 + CVF4_WF + CVF4_WOUT)  // 1441792

// ---------------- static device scratch (fp16) ----------------
__device__ __half g_comb_h[BB*KD];
__device__ __half g_w_h[W_TOTAL];
__device__ __half g_hid_h[BH];
__device__ float g_z[4][BH];          // pre-activations: 0=i, 1=o, 2=c, 3=f

// ---------------- PTX helpers (baseline ISA only) ----------------
__device__ __forceinline__ uint32_t smem_u32(const void* p) {
    return (uint32_t)__cvta_generic_to_shared(p);
}

__device__ __forceinline__ void cp16(uint32_t daddr, const void* g) {
    asm volatile("cp.async.cg.shared.global [%0], [%1], 16;" :: "r"(daddr), "l"(g) : "memory");
}
#define CP_COMMIT() asm volatile("cp.async.commit_group;" ::: "memory")
template <int N>
__device__ __forceinline__ void cp_wait() {
    asm volatile("cp.async.wait_group %0;" :: "n"(N) : "memory");
}

__device__ __forceinline__ void ldsm4(uint32_t addr, uint32_t* r) {
    asm volatile("ldmatrix.sync.aligned.m8n8.x4.shared.b16 {%0,%1,%2,%3}, [%4];"
        : "=r"(r[0]), "=r"(r[1]), "=r"(r[2]), "=r"(r[3]) : "r"(addr));
}

__device__ __forceinline__ void mma_fp16(float* c, const uint32_t* a, const uint32_t* b) {
    asm volatile("mma.sync.aligned.m16n8k16.row.col.f32.f16.f16.f32 "
        "{%0,%1,%2,%3}, {%4,%5,%6,%7}, {%8,%9}, {%0,%1,%2,%3};"
        : "+f"(c[0]), "+f"(c[1]), "+f"(c[2]), "+f"(c[3])
        : "r"(a[0]), "r"(a[1]), "r"(a[2]), "r"(a[3]), "r"(b[0]), "r"(b[1]));
}

// ---------------------------------------------------------------------------
// cp.async loader: one K-chunk (64 fp16 cols = 128B rows) of A + B tiles.
// swizzle: phys_col16 = col16 ^ (row & 7)
// ---------------------------------------------------------------------------
__device__ __forceinline__ void load_stage(uint32_t sbase,
    const char* aP, const char* bP, int lda_b, int ldb_b, int k0b, int tid) {
    const char* srcs[2] = {aP, bP};
    const int lds[2] = {lda_b, ldb_b};
#pragma unroll
    for (int t = 0; t < 2; t++) {
#pragma unroll
        for (int i = 0; i < 4; i++) {
            int idx = i * 256 + tid;
            int row = idx >> 3;
            uint32_t ch = (uint32_t)(idx & 7) * 16;
            uint32_t off = (uint32_t)row * 128 + (ch ^ (((uint32_t)row & 7) << 4));
            cp16(sbase + t * TILE_B + off,
                 srcs[t] + (size_t)row * lds[t] + k0b + ch);
        }
    }
}

// ---------------------------------------------------------------------------
// single-pass fp16 mma.sync GEMM tile: C[m,n] = sum_k A[m,k]*B[n,k] + bias[n]
// 128x128 tile, 8 warps (4Mx2N), warp tile 32x64, 3-stage, 2 CTAs/SM.
// ---------------------------------------------------------------------------
__device__ __forceinline__ void mma_gemm_tile(
    const __half* Ah, int lda, const __half* Bh, int ldb,
    const float* __restrict__ bias, float* __restrict__ C, int ldc,
    int K, int blockM, int blockN) {
    extern __shared__ __align__(1024) char dsm[];
    const int tid  = threadIdx.x;
    const int lane = tid & 31;
    const int wid  = tid >> 5;
    const int wm   = wid & 3;    // 0..3 -> 32-row slab
    const int wn   = wid >> 2;   // 0..1 -> 64-col slab
    uint32_t sb = smem_u32(dsm);

    const uint32_t a_kb = ((uint32_t)lane >> 4) * 16;          // 0/16
    const uint32_t b_kb = (((uint32_t)lane >> 3) & 1) * 16;    // 0/16
    uint32_t aRow[2], aXor[2];
#pragma unroll
    for (int mt = 0; mt < 2; mt++) {
        int r = wm * 32 + mt * 16 + (lane & 15);
        aRow[mt] = (uint32_t)r * 128;
        aXor[mt] = ((uint32_t)r & 7) << 4;
    }
    uint32_t bRow[4], bXor[4];
#pragma unroll
    for (int g = 0; g < 4; g++) {
        int r = wn * 64 + g * 16 + (((lane >> 4) << 3) + (lane & 7));
        bRow[g] = (uint32_t)r * 128;
        bXor[g] = ((uint32_t)r & 7) << 4;
    }

    float acc[2][8][4];
#pragma unroll
    for (int mt = 0; mt < 2; mt++)
#pragma unroll
        for (int nt = 0; nt < 8; nt++)
#pragma unroll
            for (int j = 0; j < 4; j++) acc[mt][nt][j] = 0.0f;

    const char* aP = (const char*)(Ah + (size_t)blockM * lda);
    const char* bP = (const char*)(Bh + (size_t)blockN * ldb);
    const int lda_b = lda * 2, ldb_b = ldb * 2;
    const int NC = K / 64;

    load_stage(sb, aP, bP, lda_b, ldb_b, 0, tid);
    CP_COMMIT();
    load_stage(sb + STAGE_B, aP, bP, lda_b, ldb_b, 128, tid);
    CP_COMMIT();

    int stage = 0;
    for (int c = 0; c < NC; ++c) {
        cp_wait<1>();
        __syncthreads();
        if (c + 2 < NC) {
            int s2 = stage + 2; if (s2 >= NSTAGE) s2 -= NSTAGE;
            load_stage(sb + (uint32_t)s2 * STAGE_B, aP, bP,
                       lda_b, ldb_b, (c + 2) * 128, tid);
        }
        CP_COMMIT();

        const uint32_t st = sb + (uint32_t)stage * STAGE_B;
#pragma unroll
        for (int kk = 0; kk < 4; kk++) {
            uint32_t a[2][4];
#pragma unroll
            for (int mt = 0; mt < 2; mt++) {
                uint32_t col = ((uint32_t)(kk * 32) + a_kb) ^ aXor[mt];
                ldsm4(st + aRow[mt] + col, a[mt]);
            }
            uint32_t b[8][2];
#pragma unroll
            for (int g = 0; g < 4; g++) {
                uint32_t col = ((uint32_t)(kk * 32) + b_kb) ^ bXor[g];
                uint32_t r[4];
                ldsm4(st + TILE_B + bRow[g] + col, r);
                b[2*g][0]   = r[0]; b[2*g][1]   = r[1];
                b[2*g+1][0] = r[2]; b[2*g+1][1] = r[3];
            }
#pragma unroll
            for (int mt = 0; mt < 2; mt++)
#pragma unroll
                for (int nt = 0; nt < 8; nt++)
                    mma_fp16(acc[mt][nt], a[mt], b[nt]);
        }
        if (++stage >= NSTAGE) stage = 0;
    }

    // epilogue: add bias, store fp32
#pragma unroll
    for (int mt = 0; mt < 2; mt++) {
        int r0 = blockM + wm * 32 + mt * 16 + (lane >> 2);
#pragma unroll
        for (int nt = 0; nt < 8; nt++) {
            int col = blockN + wn * 64 + nt * 8 + (lane & 3) * 2;
            float b0 = bias[col], b1 = bias[col + 1];
            float2 v0 = {acc[mt][nt][0] + b0, acc[mt][nt][1] + b1};
            float2 v1 = {acc[mt][nt][2] + b0, acc[mt][nt][3] + b1};
            *(float2*)(C + (size_t)r0 * ldc + col) = v0;
            *(float2*)(C + (size_t)(r0 + 8) * ldc + col) = v1;
        }
    }
}

// ---------------------------------------------------------------------------
// z order: 0 = Wf (K=1536, longest -> first), then i, o, c
__global__ __launch_bounds__(256, 2)
void gates_mma_kernel(const float* __restrict__ bi, const float* __restrict__ bo,
                      const float* __restrict__ bc, const float* __restrict__ bf) {
    int z = blockIdx.z;
    const __half* wt; const float* bias; int K; float* dst;
    if      (z == 0) { wt = g_w_h + OFF_WF; bias = bf; K = KD; dst = g_z[3]; }
    else if (z == 1) { wt = g_w_h + OFF_WI; bias = bi; K = KC; dst = g_z[0]; }
    else if (z == 2) { wt = g_w_h + OFF_WO; bias = bo; K = KC; dst = g_z[1]; }
    else             { wt = g_w_h + OFF_WC; bias = bc; K = KC; dst = g_z[2]; }
    mma_gemm_tile(g_comb_h, KD, wt, K, bias, dst, HH, K,
                  blockIdx.y * 128, blockIdx.x * 128);
}

__global__ __launch_bounds__(256, 2)
void out_mma_kernel(const float* __restrict__ bout, float* __restrict__ out) {
    mma_gemm_tile(g_hid_h, HH, g_w_h + OFF_WOUT, HH,
                  bout, out, OUTN, HH, blockIdx.y * 128, blockIdx.x * 128);
}

// ---------------------------------------------------------------------------
// merged conversion kernel: fp32 -> fp16 for combined_d AND all 5 weights.
// Flat float4 index decoded into sections.
// ---------------------------------------------------------------------------
__device__ __forceinline__ void cvt4h(float4 v, __half* dst) {
    union { __half h[4]; uint2 u; } H;
    H.h[0] = __float2half_rn(v.x);
    H.h[1] = __float2half_rn(v.y);
    H.h[2] = __float2half_rn(v.z);
    H.h[3] = __float2half_rn(v.w);
    *(uint2*)dst = H.u;
}

__global__ void conv_all_kernel(const float* __restrict__ sample,
                                const float* __restrict__ hidden,
                                const float* __restrict__ d0,
                                const float* __restrict__ Wi,
                                const float* __restrict__ Wo,
                                const float* __restrict__ Wc,
                                const float* __restrict__ Wf,
                                const float* __restrict__ Wout) {
    int idx = blockIdx.x * blockDim.x + threadIdx.x;
    if (idx >= CVF4_TOTAL) return;

    if (idx < CVF4_COMB) {
        int b  = idx / (KD / 4);
        int c4 = idx % (KD / 4);
        float4 v;
        if (c4 < INN / 4)            v = ((const float4*)sample)[b * (INN/4) + c4];
        else if (c4 < (INN+HH) / 4)  v = ((const float4*)hidden)[b * (HH/4) + (c4 - INN/4)];
        else                         v = ((const float4*)d0)[b * (HH/4) + (c4 - (INN+HH)/4)];
        cvt4h(v, g_comb_h + (size_t)idx * 4);
        return;
    }
    int r = idx - CVF4_COMB;
    const float* src; size_t off4;
    if      (r < CVF4_W1)            { src = Wi;   off4 = 0;                         }
    else if (r < 2*CVF4_W1)          { src = Wo;   off4 = CVF4_W1;   r -= CVF4_W1;   }
    else if (r < 3*CVF4_W1)          { src = Wc;   off4 = 2*CVF4_W1; r -= 2*CVF4_W1; }
    else if (r < 3*CVF4_W1+CVF4_WF)  { src = Wf;   off4 = 3*CVF4_W1; r -= 3*CVF4_W1; }
    else                             { src = Wout; off4 = 3*CVF4_W1+CVF4_WF; r -= 3*CVF4_W1+CVF4_WF; }
    float4 v = ((const float4*)src)[r];
    cvt4h(v, g_w_h + (off4 + (size_t)r) * 4);
}

// ---------------------------------------------------------------------------
// fused elementwise: 4-slice batched loads/stores (MLP=4) + streaming hints
// ---------------------------------------------------------------------------
__device__ __forceinline__ float sigf(float x) { return 1.0f / (1.0f + expf(-x)); }

__global__ void fused_cell_kernel(const float* __restrict__ cell_t,
                                  float* __restrict__ dout) {
    int idx = blockIdx.x * blockDim.x + threadIdx.x;   // over BH/4
    const int nb4 = BH / 4;
    if (idx >= nb4) return;

    const float4* c4  = (const float4*)cell_t;
    float4* hid = (float4*)(dout + (size_t)BB * OUTN);
    float4* hc  = (float4*)(dout + (size_t)2 * BB * OUTN);
    float4* dv  = (float4*)(dout + (size_t)2 * BB * OUTN + (size_t)KFR * BH);

    float4 zf = ((const float4*)g_z[3])[idx];
    float4 d;
    d.x = 0.5f * sigf(zf.x); d.y = 0.5f * sigf(zf.y);
    d.z = 0.5f * sigf(zf.z); d.w = 0.5f * sigf(zf.w);
    __stcs(&dv[idx], d);

    float4 w   = make_float4(1.f, 1.f, 1.f, 1.f);
    float4 acc = make_float4(0.f, 0.f, 0.f, 0.f);
#pragma unroll
    for (int jb = KFR - 1; jb >= 3; jb -= 4) {
        float4 buf[4];                         // 4 independent loads in flight
#pragma unroll
        for (int u = 0; u < 4; u++)
            buf[u] = __ldcs(&c4[(size_t)(jb - u) * nb4 + idx]);
#pragma unroll
        for (int u = 0; u < 4; u++) {
            int j = jb - u;
            float fi  = (float)(KFR - 1 - j);
            float inv = 1.0f / (float)(KFR - j);
            w.x *= (fi - d.x) * inv;  w.y *= (fi - d.y) * inv;
            w.z *= (fi - d.z) * inv;  w.w *= (fi - d.w) * inv;
            acc.x = fmaf(w.x, buf[u].x, acc.x);  acc.y = fmaf(w.y, buf[u].y, acc.y);
            acc.z = fmaf(w.z, buf[u].z, acc.z);  acc.w = fmaf(w.w, buf[u].w, acc.w);
            if (j >= 1) __stcs(&hc[(size_t)(j - 1) * nb4 + idx], buf[u]);
        }
    }

    float4 zi = ((const float4*)g_z[0])[idx];
    float4 zo = ((const float4*)g_z[1])[idx];
    float4 zc = ((const float4*)g_z[2])[idx];

    float4 cell;
    cell.x = -acc.x + tanhf(zc.x) * sigf(zi.x);
    cell.y = -acc.y + tanhf(zc.y) * sigf(zi.y);
    cell.z = -acc.z + tanhf(zc.z) * sigf(zi.z);
    cell.w = -acc.w + tanhf(zc.w) * sigf(zi.w);
    __stcs(&hc[(size_t)(KFR - 1) * nb4 + idx], cell);

    float4 hn;
    hn.x = tanhf(cell.x) * sigf(zo.x);
    hn.y = tanhf(cell.y) * sigf(zo.y);
    hn.z = tanhf(cell.z) * sigf(zo.z);
    hn.w = tanhf(cell.w) * sigf(zo.w);
    __stcs(&hid[idx], hn);

    cvt4h(hn, g_hid_h + (size_t)idx * 4);
}

// ---------------------------------------------------------------------------
extern "C" void kernel_launch(void* const* d_in, const int* in_sizes, int n_in,
                              void* d_out_v, int out_size) {
    const float* sample = (const float*)d_in[0];
    const float* hidden = (const float*)d_in[1];
    const float* cell_t = (const float*)d_in[2];
    const float* d0     = (const float*)d_in[3];
    const float* Wc     = (const float*)d_in[4];
    const float* bc     = (const float*)d_in[5];
    const float* Wi     = (const float*)d_in[6];
    const float* bi     = (const float*)d_in[7];
    const float* Wf     = (const float*)d_in[8];
    const float* bf     = (const float*)d_in[9];
    const float* Wo     = (const float*)d_in[10];
    const float* bo     = (const float*)d_in[11];
    const float* Wout   = (const float*)d_in[12];
    const float* bout   = (const float*)d_in[13];
    float* out = (float*)d_out_v;

    cudaFuncSetAttribute(gates_mma_kernel,
                         cudaFuncAttributeMaxDynamicSharedMemorySize, SMEM_TOT);
    cudaFuncSetAttribute(out_mma_kernel,
                         cudaFuncAttributeMaxDynamicSharedMemorySize, SMEM_TOT);

    // 1) merged fp16 conversion of combined_d + all weights
    conv_all_kernel<<<(CVF4_TOTAL + 255) / 256, 256>>>(
        sample, hidden, d0, Wi, Wo, Wc, Wf, Wout);

    // 2) 4 gate GEMMs, single-pass fp16, 2 CTAs/SM -> single wave
    dim3 ggrid(4, 16, 4);
    gates_mma_kernel<<<ggrid, 256, SMEM_TOT>>>(bi, bo, bc, bf);

    // 3) fused elementwise (batched, streaming) + fp16 hidden
    fused_cell_kernel<<<(BH / 4 + 255) / 256, 256>>>(cell_t, out);

    // 4) output GEMM
    dim3 ogrid(4, 16, 1);
    out_mma_kernel<<<ogrid, 256, SMEM_TOT>>>(bout, out);
}

// round 14
// speedup vs baseline: 2.4688x; 1.0432x over previous
#include <cuda_runtime.h>
#include <cuda_fp16.h>
#include <math.h>
#include <stdint.h>

#define BB   2048
#define INN  512
#define HH   512
#define KFR  32
#define OUTN 512
#define KD   1536            // IN + 2H (combined_d width)
#define KC   1024            // IN + H
#define BH   (BB*HH)

#define OFF_WI   0
#define OFF_WO   (512*1024)
#define OFF_WC   (2*512*1024)
#define OFF_WF   (3*512*1024)
#define OFF_WOUT (3*512*1024 + 512*1536)
#define W_TOTAL  (OFF_WOUT + 512*512)

// gates: 128x128 tile, stage = A+B = 32KB, 3 stages = 96KB -> 2 CTAs/SM
#define TILE_B   16384
#define STAGE_B  (2*TILE_B)
#define NSTAGE   3
#define SMEM_TOT (NSTAGE*STAGE_B)   // 98304

// out: 64x128 tile, stage = A 8KB + B 16KB = 24KB, 3 stages = 72KB
#define OA_TILE_B 8192
#define OB_TILE_B 16384
#define OSTAGE_B  (OA_TILE_B + OB_TILE_B)
#define OSMEM_TOT (NSTAGE*OSTAGE_B)  // 73728

// flat conversion index ranges (float4 units)
#define CVF4_COMB  (BB*KD/4)
#define CVF4_W1    (512*1024/4)
#define CVF4_WF    (512*1536/4)
#define CVF4_WOUT  (512*512/4)
#define CVF4_TOTAL (CVF4_COMB + 3*CVF4_W1 + CVF4_WF + CVF4_WOUT)

// ---------------- static device scratch (fp16) ----------------
__device__ __half g_comb_h[BB*KD];
__device__ __half g_w_h[W_TOTAL];
__device__ __half g_hid_h[BH];
__device__ float g_z[4][BH];          // pre-activations: 0=i, 1=o, 2=c, 3=f

// ---------------- PTX helpers (baseline ISA only) ----------------
__device__ __forceinline__ uint32_t smem_u32(const void* p) {
    return (uint32_t)__cvta_generic_to_shared(p);
}

__device__ __forceinline__ void cp16(uint32_t daddr, const void* g) {
    asm volatile("cp.async.cg.shared.global [%0], [%1], 16;" :: "r"(daddr), "l"(g) : "memory");
}
#define CP_COMMIT() asm volatile("cp.async.commit_group;" ::: "memory")
template <int N>
__device__ __forceinline__ void cp_wait() {
    asm volatile("cp.async.wait_group %0;" :: "n"(N) : "memory");
}

__device__ __forceinline__ void ldsm4(uint32_t addr, uint32_t* r) {
    asm volatile("ldmatrix.sync.aligned.m8n8.x4.shared.b16 {%0,%1,%2,%3}, [%4];"
        : "=r"(r[0]), "=r"(r[1]), "=r"(r[2]), "=r"(r[3]) : "r"(addr));
}

__device__ __forceinline__ void mma_fp16(float* c, const uint32_t* a, const uint32_t* b) {
    asm volatile("mma.sync.aligned.m16n8k16.row.col.f32.f16.f16.f32 "
        "{%0,%1,%2,%3}, {%4,%5,%6,%7}, {%8,%9}, {%0,%1,%2,%3};"
        : "+f"(c[0]), "+f"(c[1]), "+f"(c[2]), "+f"(c[3])
        : "r"(a[0]), "r"(a[1]), "r"(a[2]), "r"(a[3]), "r"(b[0]), "r"(b[1]));
}

// ---------------------------------------------------------------------------
// gates loader: one K-chunk (64 fp16 cols = 128B rows) of A(128) + B(128).
// swizzle: phys_col16 = col16 ^ (row & 7)
// ---------------------------------------------------------------------------
__device__ __forceinline__ void load_stage(uint32_t sbase,
    const char* aP, const char* bP, int lda_b, int ldb_b, int k0b, int tid) {
    const char* srcs[2] = {aP, bP};
    const int lds[2] = {lda_b, ldb_b};
#pragma unroll
    for (int t = 0; t < 2; t++) {
#pragma unroll
        for (int i = 0; i < 4; i++) {
            int idx = i * 256 + tid;
            int row = idx >> 3;
            uint32_t ch = (uint32_t)(idx & 7) * 16;
            uint32_t off = (uint32_t)row * 128 + (ch ^ (((uint32_t)row & 7) << 4));
            cp16(sbase + t * TILE_B + off,
                 srcs[t] + (size_t)row * lds[t] + k0b + ch);
        }
    }
}

// ---------------------------------------------------------------------------
// gates GEMM tile: 128x128, 8 warps (4Mx2N), warp tile 32x64, 3-stage.
// ---------------------------------------------------------------------------
__device__ __forceinline__ void mma_gemm_tile(
    const __half* Ah, int lda, const __half* Bh, int ldb,
    const float* __restrict__ bias, float* __restrict__ C, int ldc,
    int K, int blockM, int blockN) {
    extern __shared__ __align__(1024) char dsm[];
    const int tid  = threadIdx.x;
    const int lane = tid & 31;
    const int wid  = tid >> 5;
    const int wm   = wid & 3;
    const int wn   = wid >> 2;
    uint32_t sb = smem_u32(dsm);

    const uint32_t a_kb = ((uint32_t)lane >> 4) * 16;
    const uint32_t b_kb = (((uint32_t)lane >> 3) & 1) * 16;
    uint32_t aRow[2], aXor[2];
#pragma unroll
    for (int mt = 0; mt < 2; mt++) {
        int r = wm * 32 + mt * 16 + (lane & 15);
        aRow[mt] = (uint32_t)r * 128;
        aXor[mt] = ((uint32_t)r & 7) << 4;
    }
    uint32_t bRow[4], bXor[4];
#pragma unroll
    for (int g = 0; g < 4; g++) {
        int r = wn * 64 + g * 16 + (((lane >> 4) << 3) + (lane & 7));
        bRow[g] = (uint32_t)r * 128;
        bXor[g] = ((uint32_t)r & 7) << 4;
    }

    float acc[2][8][4];
#pragma unroll
    for (int mt = 0; mt < 2; mt++)
#pragma unroll
        for (int nt = 0; nt < 8; nt++)
#pragma unroll
            for (int j = 0; j < 4; j++) acc[mt][nt][j] = 0.0f;

    const char* aP = (const char*)(Ah + (size_t)blockM * lda);
    const char* bP = (const char*)(Bh + (size_t)blockN * ldb);
    const int lda_b = lda * 2, ldb_b = ldb * 2;
    const int NC = K / 64;

    load_stage(sb, aP, bP, lda_b, ldb_b, 0, tid);
    CP_COMMIT();
    load_stage(sb + STAGE_B, aP, bP, lda_b, ldb_b, 128, tid);
    CP_COMMIT();

    int stage = 0;
    for (int c = 0; c < NC; ++c) {
        cp_wait<1>();
        __syncthreads();
        if (c + 2 < NC) {
            int s2 = stage + 2; if (s2 >= NSTAGE) s2 -= NSTAGE;
            load_stage(sb + (uint32_t)s2 * STAGE_B, aP, bP,
                       lda_b, ldb_b, (c + 2) * 128, tid);
        }
        CP_COMMIT();

        const uint32_t st = sb + (uint32_t)stage * STAGE_B;
#pragma unroll
        for (int kk = 0; kk < 4; kk++) {
            uint32_t a[2][4];
#pragma unroll
            for (int mt = 0; mt < 2; mt++) {
                uint32_t col = ((uint32_t)(kk * 32) + a_kb) ^ aXor[mt];
                ldsm4(st + aRow[mt] + col, a[mt]);
            }
            uint32_t b[8][2];
#pragma unroll
            for (int g = 0; g < 4; g++) {
                uint32_t col = ((uint32_t)(kk * 32) + b_kb) ^ bXor[g];
                uint32_t r[4];
                ldsm4(st + TILE_B + bRow[g] + col, r);
                b[2*g][0]   = r[0]; b[2*g][1]   = r[1];
                b[2*g+1][0] = r[2]; b[2*g+1][1] = r[3];
            }
#pragma unroll
            for (int mt = 0; mt < 2; mt++)
#pragma unroll
                for (int nt = 0; nt < 8; nt++)
                    mma_fp16(acc[mt][nt], a[mt], b[nt]);
        }
        if (++stage >= NSTAGE) stage = 0;
    }

#pragma unroll
    for (int mt = 0; mt < 2; mt++) {
        int r0 = blockM + wm * 32 + mt * 16 + (lane >> 2);
#pragma unroll
        for (int nt = 0; nt < 8; nt++) {
            int col = blockN + wn * 64 + nt * 8 + (lane & 3) * 2;
            float b0 = bias[col], b1 = bias[col + 1];
            float2 v0 = {acc[mt][nt][0] + b0, acc[mt][nt][1] + b1};
            float2 v1 = {acc[mt][nt][2] + b0, acc[mt][nt][3] + b1};
            *(float2*)(C + (size_t)r0 * ldc + col) = v0;
            *(float2*)(C + (size_t)(r0 + 8) * ldc + col) = v1;
        }
    }
}

// ---------------------------------------------------------------------------
__global__ __launch_bounds__(256, 2)
void gates_mma_kernel(const float* __restrict__ bi, const float* __restrict__ bo,
                      const float* __restrict__ bc, const float* __restrict__ bf) {
    int z = blockIdx.z;
    const __half* wt; const float* bias; int K; float* dst;
    if      (z == 0) { wt = g_w_h + OFF_WF; bias = bf; K = KD; dst = g_z[3]; }
    else if (z == 1) { wt = g_w_h + OFF_WI; bias = bi; K = KC; dst = g_z[0]; }
    else if (z == 2) { wt = g_w_h + OFF_WO; bias = bo; K = KC; dst = g_z[1]; }
    else             { wt = g_w_h + OFF_WC; bias = bc; K = KC; dst = g_z[2]; }
    mma_gemm_tile(g_comb_h, KD, wt, K, bias, dst, HH, K,
                  blockIdx.y * 128, blockIdx.x * 128);
}

// ---------------------------------------------------------------------------
// out GEMM: 64x128 tile, 8 warps (2Mx4N), warp tile 32x32, 3-stage.
// grid (4, 32) = 128 CTAs -> ~87% of SMs in one wave.
// ---------------------------------------------------------------------------
__device__ __forceinline__ void load_stage_out(uint32_t sbase,
    const char* aP, const char* bP, int lda_b, int ldb_b, int k0b, int tid) {
#pragma unroll
    for (int i = 0; i < 2; i++) {          // A: 64 rows x 8 chunks = 512 cp16
        int idx = i * 256 + tid;
        int row = idx >> 3;
        uint32_t ch = (uint32_t)(idx & 7) * 16;
        uint32_t off = (uint32_t)row * 128 + (ch ^ (((uint32_t)row & 7) << 4));
        cp16(sbase + off, aP + (size_t)row * lda_b + k0b + ch);
    }
#pragma unroll
    for (int i = 0; i < 4; i++) {          // B: 128 rows x 8 chunks = 1024 cp16
        int idx = i * 256 + tid;
        int row = idx >> 3;
        uint32_t ch = (uint32_t)(idx & 7) * 16;
        uint32_t off = (uint32_t)row * 128 + (ch ^ (((uint32_t)row & 7) << 4));
        cp16(sbase + OA_TILE_B + off, bP + (size_t)row * ldb_b + k0b + ch);
    }
}

__global__ __launch_bounds__(256, 2)
void out_mma_kernel(const float* __restrict__ bout, float* __restrict__ out) {
    extern __shared__ __align__(1024) char dsm[];
    const int tid  = threadIdx.x;
    const int lane = tid & 31;
    const int wid  = tid >> 5;
    const int wm   = wid & 1;    // 0..1 -> 32-row slab
    const int wn   = wid >> 1;   // 0..3 -> 32-col slab
    const int blockM = blockIdx.y * 64;
    const int blockN = blockIdx.x * 128;
    uint32_t sb = smem_u32(dsm);

    const uint32_t a_kb = ((uint32_t)lane >> 4) * 16;
    const uint32_t b_kb = (((uint32_t)lane >> 3) & 1) * 16;
    uint32_t aRow[2], aXor[2];
#pragma unroll
    for (int mt = 0; mt < 2; mt++) {
        int r = wm * 32 + mt * 16 + (lane & 15);
        aRow[mt] = (uint32_t)r * 128;
        aXor[mt] = ((uint32_t)r & 7) << 4;
    }
    uint32_t bRow[2], bXor[2];
#pragma unroll
    for (int p = 0; p < 2; p++) {
        int r = wn * 32 + p * 16 + (((lane >> 4) << 3) + (lane & 7));
        bRow[p] = (uint32_t)r * 128;
        bXor[p] = ((uint32_t)r & 7) << 4;
    }

    float acc[2][4][4];
#pragma unroll
    for (int mt = 0; mt < 2; mt++)
#pragma unroll
        for (int nt = 0; nt < 4; nt++)
#pragma unroll
            for (int j = 0; j < 4; j++) acc[mt][nt][j] = 0.0f;

    const char* aP = (const char*)(g_hid_h + (size_t)blockM * HH);
    const char* bP = (const char*)(g_w_h + OFF_WOUT + (size_t)blockN * HH);
    const int ld_b = HH * 2;
    const int NC = HH / 64;   // 8

    load_stage_out(sb, aP, bP, ld_b, ld_b, 0, tid);
    CP_COMMIT();
    load_stage_out(sb + OSTAGE_B, aP, bP, ld_b, ld_b, 128, tid);
    CP_COMMIT();

    int stage = 0;
    for (int c = 0; c < NC; ++c) {
        cp_wait<1>();
        __syncthreads();
        if (c + 2 < NC) {
            int s2 = stage + 2; if (s2 >= NSTAGE) s2 -= NSTAGE;
            load_stage_out(sb + (uint32_t)s2 * OSTAGE_B, aP, bP,
                           ld_b, ld_b, (c + 2) * 128, tid);
        }
        CP_COMMIT();

        const uint32_t st = sb + (uint32_t)stage * OSTAGE_B;
#pragma unroll
        for (int kk = 0; kk < 4; kk++) {
            uint32_t a[2][4];
#pragma unroll
            for (int mt = 0; mt < 2; mt++) {
                uint32_t col = ((uint32_t)(kk * 32) + a_kb) ^ aXor[mt];
                ldsm4(st + aRow[mt] + col, a[mt]);
            }
            uint32_t b[4][2];
#pragma unroll
            for (int p = 0; p < 2; p++) {
                uint32_t col = ((uint32_t)(kk * 32) + b_kb) ^ bXor[p];
                uint32_t r[4];
                ldsm4(st + OA_TILE_B + bRow[p] + col, r);
                b[2*p][0]   = r[0]; b[2*p][1]   = r[1];
                b[2*p+1][0] = r[2]; b[2*p+1][1] = r[3];
            }
#pragma unroll
            for (int mt = 0; mt < 2; mt++)
#pragma unroll
                for (int nt = 0; nt < 4; nt++)
                    mma_fp16(acc[mt][nt], a[mt], b[nt]);
        }
        if (++stage >= NSTAGE) stage = 0;
    }

#pragma unroll
    for (int mt = 0; mt < 2; mt++) {
        int r0 = blockM + wm * 32 + mt * 16 + (lane >> 2);
#pragma unroll
        for (int nt = 0; nt < 4; nt++) {
            int col = blockN + wn * 32 + nt * 8 + (lane & 3) * 2;
            float b0 = bout[col], b1 = bout[col + 1];
            float2 v0 = {acc[mt][nt][0] + b0, acc[mt][nt][1] + b1};
            float2 v1 = {acc[mt][nt][2] + b0, acc[mt][nt][3] + b1};
            *(float2*)(out + (size_t)r0 * OUTN + col) = v0;
            *(float2*)(out + (size_t)(r0 + 8) * OUTN + col) = v1;
        }
    }
}

// ---------------------------------------------------------------------------
// merged conversion kernel: fp32 -> fp16 for combined_d AND all 5 weights.
// ---------------------------------------------------------------------------
__device__ __forceinline__ void cvt4h(float4 v, __half* dst) {
    union { __half h[4]; uint2 u; } H;
    H.h[0] = __float2half_rn(v.x);
    H.h[1] = __float2half_rn(v.y);
    H.h[2] = __float2half_rn(v.z);
    H.h[3] = __float2half_rn(v.w);
    *(uint2*)dst = H.u;
}

__global__ void conv_all_kernel(const float* __restrict__ sample,
                                const float* __restrict__ hidden,
                                const float* __restrict__ d0,
                                const float* __restrict__ Wi,
                                const float* __restrict__ Wo,
                                const float* __restrict__ Wc,
                                const float* __restrict__ Wf,
                                const float* __restrict__ Wout) {
    int idx = blockIdx.x * blockDim.x + threadIdx.x;
    if (idx >= CVF4_TOTAL) return;

    if (idx < CVF4_COMB) {
        int b  = idx / (KD / 4);
        int c4 = idx % (KD / 4);
        float4 v;
        if (c4 < INN / 4)            v = ((const float4*)sample)[b * (INN/4) + c4];
        else if (c4 < (INN+HH) / 4)  v = ((const float4*)hidden)[b * (HH/4) + (c4 - INN/4)];
        else                         v = ((const float4*)d0)[b * (HH/4) + (c4 - (INN+HH)/4)];
        cvt4h(v, g_comb_h + (size_t)idx * 4);
        return;
    }
    int r = idx - CVF4_COMB;
    const float* src; size_t off4;
    if      (r < CVF4_W1)            { src = Wi;   off4 = 0;                         }
    else if (r < 2*CVF4_W1)          { src = Wo;   off4 = CVF4_W1;   r -= CVF4_W1;   }
    else if (r < 3*CVF4_W1)          { src = Wc;   off4 = 2*CVF4_W1; r -= 2*CVF4_W1; }
    else if (r < 3*CVF4_W1+CVF4_WF)  { src = Wf;   off4 = 3*CVF4_W1; r -= 3*CVF4_W1; }
    else                             { src = Wout; off4 = 3*CVF4_W1+CVF4_WF; r -= 3*CVF4_W1+CVF4_WF; }
    float4 v = ((const float4*)src)[r];
    cvt4h(v, g_w_h + (off4 + (size_t)r) * 4);
}

// ---------------------------------------------------------------------------
// fused elementwise: 4-slice batched loads/stores (MLP=4) + streaming hints
// ---------------------------------------------------------------------------
__device__ __forceinline__ float sigf(float x) { return 1.0f / (1.0f + expf(-x)); }

__global__ void fused_cell_kernel(const float* __restrict__ cell_t,
                                  float* __restrict__ dout) {
    int idx = blockIdx.x * blockDim.x + threadIdx.x;   // over BH/4
    const int nb4 = BH / 4;
    if (idx >= nb4) return;

    const float4* c4  = (const float4*)cell_t;
    float4* hid = (float4*)(dout + (size_t)BB * OUTN);
    float4* hc  = (float4*)(dout + (size_t)2 * BB * OUTN);
    float4* dv  = (float4*)(dout + (size_t)2 * BB * OUTN + (size_t)KFR * BH);

    float4 zf = ((const float4*)g_z[3])[idx];
    float4 d;
    d.x = 0.5f * sigf(zf.x); d.y = 0.5f * sigf(zf.y);
    d.z = 0.5f * sigf(zf.z); d.w = 0.5f * sigf(zf.w);
    __stcs(&dv[idx], d);

    float4 w   = make_float4(1.f, 1.f, 1.f, 1.f);
    float4 acc = make_float4(0.f, 0.f, 0.f, 0.f);
#pragma unroll
    for (int jb = KFR - 1; jb >= 3; jb -= 4) {
        float4 buf[4];
#pragma unroll
        for (int u = 0; u < 4; u++)
            buf[u] = __ldcs(&c4[(size_t)(jb - u) * nb4 + idx]);
#pragma unroll
        for (int u = 0; u < 4; u++) {
            int j = jb - u;
            float fi  = (float)(KFR - 1 - j);
            float inv = 1.0f / (float)(KFR - j);
            w.x *= (fi - d.x) * inv;  w.y *= (fi - d.y) * inv;
            w.z *= (fi - d.z) * inv;  w.w *= (fi - d.w) * inv;
            acc.x = fmaf(w.x, buf[u].x, acc.x);  acc.y = fmaf(w.y, buf[u].y, acc.y);
            acc.z = fmaf(w.z, buf[u].z, acc.z);  acc.w = fmaf(w.w, buf[u].w, acc.w);
            if (j >= 1) __stcs(&hc[(size_t)(j - 1) * nb4 + idx], buf[u]);
        }
    }

    float4 zi = ((const float4*)g_z[0])[idx];
    float4 zo = ((const float4*)g_z[1])[idx];
    float4 zc = ((const float4*)g_z[2])[idx];

    float4 cell;
    cell.x = -acc.x + tanhf(zc.x) * sigf(zi.x);
    cell.y = -acc.y + tanhf(zc.y) * sigf(zi.y);
    cell.z = -acc.z + tanhf(zc.z) * sigf(zi.z);
    cell.w = -acc.w + tanhf(zc.w) * sigf(zi.w);
    __stcs(&hc[(size_t)(KFR - 1) * nb4 + idx], cell);

    float4 hn;
    hn.x = tanhf(cell.x) * sigf(zo.x);
    hn.y = tanhf(cell.y) * sigf(zo.y);
    hn.z = tanhf(cell.z) * sigf(zo.z);
    hn.w = tanhf(cell.w) * sigf(zo.w);
    __stcs(&hid[idx], hn);

    cvt4h(hn, g_hid_h + (size_t)idx * 4);
}

// ---------------------------------------------------------------------------
extern "C" void kernel_launch(void* const* d_in, const int* in_sizes, int n_in,
                              void* d_out_v, int out_size) {
    const float* sample = (const float*)d_in[0];
    const float* hidden = (const float*)d_in[1];
    const float* cell_t = (const float*)d_in[2];
    const float* d0     = (const float*)d_in[3];
    const float* Wc     = (const float*)d_in[4];
    const float* bc     = (const float*)d_in[5];
    const float* Wi     = (const float*)d_in[6];
    const float* bi     = (const float*)d_in[7];
    const float* Wf     = (const float*)d_in[8];
    const float* bf     = (const float*)d_in[9];
    const float* Wo     = (const float*)d_in[10];
    const float* bo     = (const float*)d_in[11];
    const float* Wout   = (const float*)d_in[12];
    const float* bout   = (const float*)d_in[13];
    float* out = (float*)d_out_v;

    cudaFuncSetAttribute(gates_mma_kernel,
                         cudaFuncAttributeMaxDynamicSharedMemorySize, SMEM_TOT);
    cudaFuncSetAttribute(out_mma_kernel,
                         cudaFuncAttributeMaxDynamicSharedMemorySize, OSMEM_TOT);

    // 1) merged fp16 conversion of combined_d + all weights
    conv_all_kernel<<<(CVF4_TOTAL + 255) / 256, 256>>>(
        sample, hidden, d0, Wi, Wo, Wc, Wf, Wout);

    // 2) 4 gate GEMMs, single-pass fp16, 2 CTAs/SM -> single wave
    dim3 ggrid(4, 16, 4);
    gates_mma_kernel<<<ggrid, 256, SMEM_TOT>>>(bi, bo, bc, bf);

    // 3) fused elementwise (batched, streaming) + fp16 hidden
    fused_cell_kernel<<<(BH / 4 + 255) / 256, 256>>>(cell_t, out);

    // 4) output GEMM, 64x128 tiles -> 128 CTAs
    dim3 ogrid(4, 32);
    out_mma_kernel<<<ogrid, 256, OSMEM_TOT>>>(bout, out);
}